// round 5
// baseline (speedup 1.0000x reference)
#include <cuda_runtime.h>
#include <cuda_fp16.h>
#include <cuda_fp8.h>
#include <math.h>
#include <stdint.h>

// ---------------- problem constants ----------------
#define B_  16
#define N_  1024
#define D_  64
#define EPS_ 0.1f
#define TOTAL_ROWS (B_*N_)        // 16384
#define NBLK 148
#define NTHR 1024
#define BAR_STRIDE 32             // 128B between flags

// ---------------- device scratch (static, no allocs) ----------------
__device__ __half g_sxh[TOTAL_ROWS*D_];            // softmax(x) fp16  2MB
__device__ __half g_syh[TOTAL_ROWS*D_];            // softmax(y) fp16  2MB
__device__ float  g_x2[TOTAL_ROWS];
__device__ float  g_y2[TOTAL_ROWS];
__device__ unsigned char g_K8[(size_t)B_*N_*N_];   // K = exp(-10C)  e4m3, 16MB
__device__ unsigned char g_P8[(size_t)B_*N_*N_];   // P = 10*C*K     e4m3, 16MB
__device__ float  g_a[TOTAL_ROWS];
__device__ float  g_b[TOTAL_ROWS];
__device__ float  g_du[TOTAL_ROWS];
__device__ unsigned g_flags[NBLK*BAR_STRIDE];      // barrier flags (zero-init)
__device__ unsigned g_gen2;                        // barrier generation
__device__ int g_stop;

// ---------------- helpers ----------------
__device__ __forceinline__ uint32_t smem_u32(const void* p) {
    uint32_t a;
    asm("{ .reg .u64 t; cvta.to.shared.u64 t, %1; cvt.u32.u64 %0, t; }" : "=r"(a) : "l"(p));
    return a;
}
__device__ __forceinline__ void ldsm_x4(uint32_t& r0, uint32_t& r1, uint32_t& r2, uint32_t& r3,
                                        uint32_t addr) {
    asm volatile("ldmatrix.sync.aligned.m8n8.x4.shared.b16 {%0,%1,%2,%3}, [%4];"
                 : "=r"(r0), "=r"(r1), "=r"(r2), "=r"(r3) : "r"(addr));
}
__device__ __forceinline__ void mma16816(float* c, const uint32_t* a, const uint32_t* b) {
    asm volatile(
        "mma.sync.aligned.m16n8k16.row.col.f32.f16.f16.f32 "
        "{%0,%1,%2,%3}, {%4,%5,%6,%7}, {%8,%9}, {%0,%1,%2,%3};"
        : "+f"(c[0]), "+f"(c[1]), "+f"(c[2]), "+f"(c[3])
        : "r"(a[0]), "r"(a[1]), "r"(a[2]), "r"(a[3]), "r"(b[0]), "r"(b[1]));
}
__device__ __forceinline__ float2 fp8x2_f2(unsigned short s) {
    __half2_raw hr = __nv_cvt_fp8x2_to_halfraw2((__nv_fp8x2_storage_t)s, __NV_E4M3);
    return __half22float2(*reinterpret_cast<__half2*>(&hr));
}
__device__ __forceinline__ unsigned short f2_fp8x2(float a, float b) {
    float2 f; f.x = a; f.y = b;
    return (unsigned short)__nv_cvt_float2_to_fp8x2(f, __NV_SATFINITE, __NV_E4M3);
}
// exp(t) for t in [-60, 0]; deg-5 poly + exponent splice; no MUFU.
__device__ __forceinline__ float exp_neg(float t) {
    float z = fmaf(t, 1.44269504f, 12582912.0f);   // t*log2e + 1.5*2^23 (RNE)
    float r = z - 12582912.0f;                     // round(t*log2e)
    float f = fmaf(t, 1.44269504f, -r);            // frac in [-0.5, 0.5]
    float g = f * 0.69314718f;
    float p = fmaf(g, 8.3333337e-3f, 4.1666668e-2f);
    p = fmaf(p, g, 0.16666667f);
    p = fmaf(p, g, 0.5f);
    p = fmaf(p, g, 1.0f);
    p = fmaf(p, g, 1.0f);
    uint32_t sb = (__float_as_uint(z) + 127u) << 23;   // 2^round bits
    return p * __uint_as_float(sb);
}

// ---------------- softmax: 4 rows/warp, fp16 outputs + fp32 norms ----------
__global__ __launch_bounds__(256) void softmax_kernel(const float* __restrict__ x,
                                                      const float* __restrict__ y) {
    int w    = (blockIdx.x * blockDim.x + threadIdx.x) >> 5;   // 0..8191
    int lane = threadIdx.x & 31;
    const float* src; __half* dst; float* nrm; int r0;
    if (w < 4096) { src = x; dst = g_sxh; nrm = g_x2; r0 = w << 2; }
    else          { src = y; dst = g_syh; nrm = g_y2; r0 = (w - 4096) << 2; }
    float2 v[4];
    #pragma unroll
    for (int q = 0; q < 4; q++)
        v[q] = ((const float2*)(src + (size_t)(r0 + q) * D_))[lane];
    float m[4], s[4];
    #pragma unroll
    for (int q = 0; q < 4; q++) m[q] = fmaxf(v[q].x, v[q].y);
    #pragma unroll
    for (int o = 16; o; o >>= 1)
        #pragma unroll
        for (int q = 0; q < 4; q++) m[q] = fmaxf(m[q], __shfl_xor_sync(0xffffffffu, m[q], o));
    float e0[4], e1[4];
    #pragma unroll
    for (int q = 0; q < 4; q++) {
        e0[q] = __expf(v[q].x - m[q]);
        e1[q] = __expf(v[q].y - m[q]);
        s[q] = e0[q] + e1[q];
    }
    #pragma unroll
    for (int o = 16; o; o >>= 1)
        #pragma unroll
        for (int q = 0; q < 4; q++) s[q] += __shfl_xor_sync(0xffffffffu, s[q], o);
    float n[4];
    #pragma unroll
    for (int q = 0; q < 4; q++) {
        float inv = 1.0f / s[q];
        float p0 = e0[q] * inv, p1 = e1[q] * inv;
        ((__half2*)dst)[(size_t)(r0 + q) * 32 + lane] = __floats2half2_rn(p0, p1);
        n[q] = p0 * p0 + p1 * p1;
    }
    #pragma unroll
    for (int o = 16; o; o >>= 1)
        #pragma unroll
        for (int q = 0; q < 4; q++) n[q] += __shfl_xor_sync(0xffffffffu, n[q], o);
    if (lane == 0)
        #pragma unroll
        for (int q = 0; q < 4; q++) nrm[r0 + q] = n[q];
}

// ---------------- cost kernel: HMMA + fused exp -> fp8 K and P ------------
__global__ __launch_bounds__(256) void cost_kernel() {
    __shared__ __half As[128][72];
    __shared__ __half Bs[64][72];
    __shared__ float  yn[64];        // -10 * y2
    const int tid = threadIdx.x, warp = tid >> 5, lane = tid & 31;
    const int jt = blockIdx.x, it = blockIdx.y, b = blockIdx.z;
    const int i_base = (b << 10) + (it << 7);
    const int j_base = (b << 10) + (jt << 6);

    #pragma unroll
    for (int q = 0; q < 4; q++) {
        int idx = tid + (q << 8);
        int r = idx >> 3, ch = idx & 7;
        *(uint4*)&As[r][ch << 3] = ((const uint4*)(g_sxh + (size_t)(i_base + r) * D_))[ch];
    }
    #pragma unroll
    for (int q = 0; q < 2; q++) {
        int idx = tid + (q << 8);
        int r = idx >> 3, ch = idx & 7;
        *(uint4*)&Bs[r][ch << 3] = ((const uint4*)(g_syh + (size_t)(j_base + r) * D_))[ch];
    }
    if (tid < 64) yn[tid] = -10.0f * g_y2[j_base + tid];
    __syncthreads();

    const int wr = warp & 3, wc = warp >> 2;
    const int m0 = wr << 5, n0 = wc << 5;

    float acc[2][4][4];
    #pragma unroll
    for (int mt = 0; mt < 2; mt++)
        #pragma unroll
        for (int nt = 0; nt < 4; nt++)
            #pragma unroll
            for (int e = 0; e < 4; e++) acc[mt][nt][e] = 0.f;

    #pragma unroll
    for (int ks = 0; ks < 4; ks++) {
        const int k0 = ks << 4;
        uint32_t af[2][4], bf[4][2];
        #pragma unroll
        for (int mt = 0; mt < 2; mt++) {
            uint32_t addr = smem_u32(&As[m0 + (mt << 4) + (lane & 15)][k0 + ((lane >> 4) << 3)]);
            ldsm_x4(af[mt][0], af[mt][1], af[mt][2], af[mt][3], addr);
        }
        #pragma unroll
        for (int np = 0; np < 2; np++) {
            int mat = lane >> 3, rin = lane & 7;
            int row = n0 + (np << 4) + ((mat >> 1) << 3) + rin;
            int col = k0 + ((mat & 1) << 3);
            uint32_t addr = smem_u32(&Bs[row][col]);
            uint32_t r0, r1, r2, r3;
            ldsm_x4(r0, r1, r2, r3, addr);
            bf[np * 2][0] = r0; bf[np * 2][1] = r1;
            bf[np * 2 + 1][0] = r2; bf[np * 2 + 1][1] = r3;
        }
        #pragma unroll
        for (int mt = 0; mt < 2; mt++)
            #pragma unroll
            for (int nt = 0; nt < 4; nt++)
                mma16816(acc[mt][nt], af[mt], bf[nt]);
    }

    // epilogue: t = -10C = -10(x2+y2) + 20s ; K = exp(t) ; P = -t*K
    const int g = lane >> 2, tq = lane & 3;
    #pragma unroll
    for (int mt = 0; mt < 2; mt++) {
        int gi0 = i_base + m0 + (mt << 4) + g;
        int gi1 = gi0 + 8;
        float xa0 = -10.0f * g_x2[gi0], xa1 = -10.0f * g_x2[gi1];
        unsigned char* k0p = g_K8 + ((size_t)gi0 << 10) + (jt << 6);
        unsigned char* k1p = g_K8 + ((size_t)gi1 << 10) + (jt << 6);
        unsigned char* p0p = g_P8 + ((size_t)gi0 << 10) + (jt << 6);
        unsigned char* p1p = g_P8 + ((size_t)gi1 << 10) + (jt << 6);
        #pragma unroll
        for (int nt = 0; nt < 4; nt++) {
            int jl = n0 + (nt << 3) + (tq << 1);
            float y0 = yn[jl], y1 = yn[jl + 1];
            float t00 = fmaf(20.0f, acc[mt][nt][0], xa0 + y0);
            float t01 = fmaf(20.0f, acc[mt][nt][1], xa0 + y1);
            float t10 = fmaf(20.0f, acc[mt][nt][2], xa1 + y0);
            float t11 = fmaf(20.0f, acc[mt][nt][3], xa1 + y1);
            t00 = fminf(t00, 0.0f); t01 = fminf(t01, 0.0f);
            t10 = fminf(t10, 0.0f); t11 = fminf(t11, 0.0f);
            float k00 = exp_neg(t00), k01 = exp_neg(t01);
            float k10 = exp_neg(t10), k11 = exp_neg(t11);
            *(unsigned short*)(k0p + jl) = f2_fp8x2(k00, k01);
            *(unsigned short*)(k1p + jl) = f2_fp8x2(k10, k11);
            *(unsigned short*)(p0p + jl) = f2_fp8x2(-t00 * k00, -t01 * k01);
            *(unsigned short*)(p1p + jl) = f2_fp8x2(-t10 * k10, -t11 * k11);
        }
    }
}

// ---------------- flag-array grid barrier ----------------
__device__ __forceinline__ void grid_sync(unsigned tgt) {
    __syncthreads();
    if (blockIdx.x == 0) {
        if (threadIdx.x > 0 && threadIdx.x < NBLK) {
            while (((volatile unsigned*)g_flags)[threadIdx.x * BAR_STRIDE] < tgt) { }
        }
        __threadfence();
        __syncthreads();
        if (threadIdx.x == 0) *(volatile unsigned*)&g_gen2 = tgt;
        __syncthreads();
    } else {
        if (threadIdx.x == 0) {
            __threadfence();
            ((volatile unsigned*)g_flags)[blockIdx.x * BAR_STRIDE] = tgt;
            while (*(volatile unsigned*)&g_gen2 < tgt) { }
            __threadfence();
        }
        __syncthreads();
    }
}

// ---------------- persistent Sinkhorn loop + final cost ----------------
// smem: [0..2047] b-stage (row/final passes) / [0..1023] a-stage (col pass)
//       [1024..9215] col partials (64 grp x 128 col), [9216..10239] stage2
__global__ __launch_bounds__(NTHR, 1) void sinkhorn_kernel(float* __restrict__ out) {
    __shared__ __align__(16) float sbuf[10240];
    const int tid = threadIdx.x, blk = blockIdx.x;
    const int lane = tid & 31, warp = tid >> 5;
    const float mu = 1.0f / 1024.0f + 1e-8f;
    const float log_mu = logf(mu);

    unsigned bar = *(volatile unsigned*)&g_gen2;    // stable pre-launch value

    {
        int gg = blk * NTHR + tid;
        if (gg < TOTAL_ROWS) { g_a[gg] = 1.0f; g_b[gg] = 1.0f; }
        if (blk == 0 && tid == 0) g_stop = 0;
    }
    grid_sync(++bar);

    const int chunk = (TOTAL_ROWS + NBLK - 1) / NBLK;   // 111
    const int rs = blk * chunk;
    const int re = min(rs + chunk, TOTAL_ROWS);
    const int b0 = rs >> 10;
    const int nstage = (rs < re) ? ((((re - 1) >> 10) - b0 + 1) << 10) : 0;

    for (int it = 0; it < 100; ++it) {
        // ---- row pass: s_i = sum_j K_ij b_j ; update a, |du| ----
        if (rs < re) {
            for (int idx = tid; idx < nstage; idx += NTHR)
                sbuf[idx] = __ldcg(&g_b[(b0 << 10) + idx]);
            __syncthreads();
            for (int r = rs + warp; r < re; r += 32) {
                const float* bs = sbuf + (((r >> 10) - b0) << 10);
                const uint4* Kr = (const uint4*)(g_K8 + ((size_t)r << 10));
                float acc = 0.f;
                #pragma unroll
                for (int k = 0; k < 2; k++) {
                    int u = lane + (k << 5);
                    uint4 v = Kr[u];
                    const float4* bp = (const float4*)(bs + (u << 4));
                    float4 q0 = bp[0], q1 = bp[1], q2 = bp[2], q3 = bp[3];
                    float2 f0 = fp8x2_f2((unsigned short)(v.x & 0xFFFF));
                    float2 f1 = fp8x2_f2((unsigned short)(v.x >> 16));
                    float2 f2 = fp8x2_f2((unsigned short)(v.y & 0xFFFF));
                    float2 f3 = fp8x2_f2((unsigned short)(v.y >> 16));
                    float2 f4 = fp8x2_f2((unsigned short)(v.z & 0xFFFF));
                    float2 f5 = fp8x2_f2((unsigned short)(v.z >> 16));
                    float2 f6 = fp8x2_f2((unsigned short)(v.w & 0xFFFF));
                    float2 f7 = fp8x2_f2((unsigned short)(v.w >> 16));
                    acc = fmaf(f0.x, q0.x, fmaf(f0.y, q0.y, fmaf(f1.x, q0.z, fmaf(f1.y, q0.w, acc))));
                    acc = fmaf(f2.x, q1.x, fmaf(f2.y, q1.y, fmaf(f3.x, q1.z, fmaf(f3.y, q1.w, acc))));
                    acc = fmaf(f4.x, q2.x, fmaf(f4.y, q2.y, fmaf(f5.x, q2.z, fmaf(f5.y, q2.w, acc))));
                    acc = fmaf(f6.x, q3.x, fmaf(f6.y, q3.y, fmaf(f7.x, q3.z, fmaf(f7.y, q3.w, acc))));
                }
                #pragma unroll
                for (int o = 16; o; o >>= 1) acc += __shfl_xor_sync(0xffffffffu, acc, o);
                if (lane == 0) {
                    float aold = __ldcg(&g_a[r]);
                    float as = fmaf(aold, acc, 1e-6f);
                    float du = EPS_ * (log_mu - __logf(as));
                    __stcg(&g_a[r], mu * aold / as);
                    __stcg(&g_du[r], fabsf(du));
                }
            }
        }
        grid_sync(++bar);
        // ---- col pass (blocks 0..127): t_j = sum_i K_ij a_i ; update b ----
        if (blk < 128) {
            int bb = blk >> 3, j0 = (blk & 7) << 7;
            sbuf[tid] = __ldcg(&g_a[(bb << 10) + tid]);
            __syncthreads();
            int jc = tid & 15, ig = tid >> 4;       // 16 uint2-strips x 64 i-groups
            float acc[8] = {0.f,0.f,0.f,0.f,0.f,0.f,0.f,0.f};
            const unsigned char* base = g_K8 + ((size_t)bb << 20) + j0 + (jc << 3);
            #pragma unroll 4
            for (int i = ig; i < 1024; i += 64) {
                uint2 v = *(const uint2*)(base + ((size_t)i << 10));
                float ai = sbuf[i];
                float2 f0 = fp8x2_f2((unsigned short)(v.x & 0xFFFF));
                float2 f1 = fp8x2_f2((unsigned short)(v.x >> 16));
                float2 f2 = fp8x2_f2((unsigned short)(v.y & 0xFFFF));
                float2 f3 = fp8x2_f2((unsigned short)(v.y >> 16));
                acc[0] = fmaf(f0.x, ai, acc[0]); acc[1] = fmaf(f0.y, ai, acc[1]);
                acc[2] = fmaf(f1.x, ai, acc[2]); acc[3] = fmaf(f1.y, ai, acc[3]);
                acc[4] = fmaf(f2.x, ai, acc[4]); acc[5] = fmaf(f2.y, ai, acc[5]);
                acc[6] = fmaf(f3.x, ai, acc[6]); acc[7] = fmaf(f3.y, ai, acc[7]);
            }
            float* sred = sbuf + 1024;
            *(float4*)(sred + (ig << 7) + (jc << 3))     = make_float4(acc[0], acc[1], acc[2], acc[3]);
            *(float4*)(sred + (ig << 7) + (jc << 3) + 4) = make_float4(acc[4], acc[5], acc[6], acc[7]);
            __syncthreads();
            {   // two-stage reduce over 64 groups
                int j = tid & 127, seg = tid >> 7;  // 8 segs x 8 groups
                float p = 0.f;
                #pragma unroll
                for (int q = 0; q < 8; q++) p += sred[((seg << 3) + q) * 128 + j];
                sbuf[9216 + (seg << 7) + j] = p;
            }
            __syncthreads();
            if (tid < 128) {
                float t = 0.f;
                #pragma unroll
                for (int q = 0; q < 8; q++) t += sbuf[9216 + (q << 7) + tid];
                int j = (bb << 10) + j0 + tid;
                float bold = __ldcg(&g_b[j]);
                float bt = fmaf(bold, t, 1e-6f);
                __stcg(&g_b[j], mu * bold / bt);
            }
        } else if (blk == 128) {
            float s = 0.f;
            #pragma unroll
            for (int k = 0; k < 16; k++) s += __ldcg(&g_du[tid + (k << 10)]);
            sbuf[tid] = s;
            __syncthreads();
            for (int off = 512; off; off >>= 1) {
                if (tid < off) sbuf[tid] += sbuf[tid + off];
                __syncthreads();
            }
            if (tid == 0) g_stop = (sbuf[0] * (1.0f / 16.0f) < 0.1f) ? 1 : 0;
        }
        grid_sync(++bar);
        if (*((volatile int*)&g_stop)) break;
    }

    // ---- final: cost_b = 0.1 * sum a_i P_ij b_j ; out = mean ----
    if (rs < re) {
        __syncthreads();
        for (int idx = tid; idx < nstage; idx += NTHR)
            sbuf[idx] = __ldcg(&g_b[(b0 << 10) + idx]);
        __syncthreads();
        for (int r = rs + warp; r < re; r += 32) {
            const float* bs = sbuf + (((r >> 10) - b0) << 10);
            const uint4* Pr = (const uint4*)(g_P8 + ((size_t)r << 10));
            float acc = 0.f;
            #pragma unroll
            for (int k = 0; k < 2; k++) {
                int u = lane + (k << 5);
                uint4 v = Pr[u];
                const float4* bp = (const float4*)(bs + (u << 4));
                float4 q0 = bp[0], q1 = bp[1], q2 = bp[2], q3 = bp[3];
                float2 f0 = fp8x2_f2((unsigned short)(v.x & 0xFFFF));
                float2 f1 = fp8x2_f2((unsigned short)(v.x >> 16));
                float2 f2 = fp8x2_f2((unsigned short)(v.y & 0xFFFF));
                float2 f3 = fp8x2_f2((unsigned short)(v.y >> 16));
                float2 f4 = fp8x2_f2((unsigned short)(v.z & 0xFFFF));
                float2 f5 = fp8x2_f2((unsigned short)(v.z >> 16));
                float2 f6 = fp8x2_f2((unsigned short)(v.w & 0xFFFF));
                float2 f7 = fp8x2_f2((unsigned short)(v.w >> 16));
                acc = fmaf(f0.x, q0.x, fmaf(f0.y, q0.y, fmaf(f1.x, q0.z, fmaf(f1.y, q0.w, acc))));
                acc = fmaf(f2.x, q1.x, fmaf(f2.y, q1.y, fmaf(f3.x, q1.z, fmaf(f3.y, q1.w, acc))));
                acc = fmaf(f4.x, q2.x, fmaf(f4.y, q2.y, fmaf(f5.x, q2.z, fmaf(f5.y, q2.w, acc))));
                acc = fmaf(f6.x, q3.x, fmaf(f6.y, q3.y, fmaf(f7.x, q3.z, fmaf(f7.y, q3.w, acc))));
            }
            #pragma unroll
            for (int o = 16; o; o >>= 1) acc += __shfl_xor_sync(0xffffffffu, acc, o);
            if (lane == 0)
                __stcg(&g_du[r], __ldcg(&g_a[r]) * acc);
        }
    }
    grid_sync(++bar);
    if (blk == 0) {
        float s = 0.f;
        #pragma unroll
        for (int k = 0; k < 16; k++) s += __ldcg(&g_du[tid + (k << 10)]);
        sbuf[tid] = s;
        __syncthreads();
        for (int off = 512; off; off >>= 1) {
            if (tid < off) sbuf[tid] += sbuf[tid + off];
            __syncthreads();
        }
        if (tid == 0) out[0] = sbuf[0] * (EPS_ / 16.0f);   // (0.1 * sum aPb)/16
    }
}

// ---------------- launch ----------------
extern "C" void kernel_launch(void* const* d_in, const int* in_sizes, int n_in,
                              void* d_out, int out_size) {
    const float* x = (const float*)d_in[0];
    const float* y = (const float*)d_in[1];
    (void)in_sizes; (void)n_in; (void)out_size;

    softmax_kernel<<<1024, 256>>>(x, y);
    dim3 gc(16, 8, 16);   // (j-tiles of 64, i-tiles of 128, batch)
    cost_kernel<<<gc, 256>>>();
    sinkhorn_kernel<<<NBLK, NTHR>>>((float*)d_out);
}

// round 7
// speedup vs baseline: 1.1790x; 1.1790x over previous
#include <cuda_runtime.h>
#include <cuda_fp16.h>
#include <math.h>
#include <stdint.h>

// ---------------- problem constants ----------------
#define B_  16
#define N_  1024
#define D_  64
#define EPS_ 0.1f
#define TOTAL_ROWS (B_*N_)        // 16384
#define NBLK 148
#define NTHR 1024
#define CHUNK 111                 // rows per block (148*111 >= 16384)
#define BAR_STRIDE 32             // 128B between barrier flags

// ---------------- device scratch (static, no allocs) ----------------
__device__ __half g_sxh[TOTAL_ROWS*D_];            // softmax(x) fp16  2MB
__device__ __half g_syh[TOTAL_ROWS*D_];            // softmax(y) fp16  2MB
__device__ float  g_x2[TOTAL_ROWS];
__device__ float  g_y2[TOTAL_ROWS];
__device__ __half g_Kh[(size_t)B_*N_*N_];          // K = exp(-10C) fp16, 32MB
__device__ float  g_b[TOTAL_ROWS];
__device__ float  g_du[TOTAL_ROWS];
__device__ float  g_tp[NBLK*2048];                 // per-block col partials
__device__ unsigned g_flags[NBLK*BAR_STRIDE];      // barrier flags (monotonic)
__device__ unsigned g_gen2;                        // barrier generation
__device__ int g_stop;

// ---------------- helpers ----------------
__device__ __forceinline__ uint32_t smem_u32(const void* p) {
    uint32_t a;
    asm("{ .reg .u64 t; cvta.to.shared.u64 t, %1; cvt.u32.u64 %0, t; }" : "=r"(a) : "l"(p));
    return a;
}
__device__ __forceinline__ void ldsm_x4(uint32_t& r0, uint32_t& r1, uint32_t& r2, uint32_t& r3,
                                        uint32_t addr) {
    asm volatile("ldmatrix.sync.aligned.m8n8.x4.shared.b16 {%0,%1,%2,%3}, [%4];"
                 : "=r"(r0), "=r"(r1), "=r"(r2), "=r"(r3) : "r"(addr));
}
__device__ __forceinline__ void mma16816(float* c, const uint32_t* a, const uint32_t* b) {
    asm volatile(
        "mma.sync.aligned.m16n8k16.row.col.f32.f16.f16.f32 "
        "{%0,%1,%2,%3}, {%4,%5,%6,%7}, {%8,%9}, {%0,%1,%2,%3};"
        : "+f"(c[0]), "+f"(c[1]), "+f"(c[2]), "+f"(c[3])
        : "r"(a[0]), "r"(a[1]), "r"(a[2]), "r"(a[3]), "r"(b[0]), "r"(b[1]));
}

// ---------------- softmax: 4 rows/warp (MLP), fp16 out + fp32 norms -------
__global__ __launch_bounds__(256) void softmax_kernel(const float* __restrict__ x,
                                                      const float* __restrict__ y) {
    int w    = (blockIdx.x * blockDim.x + threadIdx.x) >> 5;   // 0..8191
    int lane = threadIdx.x & 31;
    const float* src; __half* dst; float* nrm; int r0;
    if (w < 4096) { src = x; dst = g_sxh; nrm = g_x2; r0 = w << 2; }
    else          { src = y; dst = g_syh; nrm = g_y2; r0 = (w - 4096) << 2; }
    float2 v[4];
    #pragma unroll
    for (int q = 0; q < 4; q++)
        v[q] = ((const float2*)(src + (size_t)(r0 + q) * D_))[lane];
    float m[4], s[4];
    #pragma unroll
    for (int q = 0; q < 4; q++) m[q] = fmaxf(v[q].x, v[q].y);
    #pragma unroll
    for (int o = 16; o; o >>= 1)
        #pragma unroll
        for (int q = 0; q < 4; q++) m[q] = fmaxf(m[q], __shfl_xor_sync(0xffffffffu, m[q], o));
    float e0[4], e1[4];
    #pragma unroll
    for (int q = 0; q < 4; q++) {
        e0[q] = __expf(v[q].x - m[q]);
        e1[q] = __expf(v[q].y - m[q]);
        s[q] = e0[q] + e1[q];
    }
    #pragma unroll
    for (int o = 16; o; o >>= 1)
        #pragma unroll
        for (int q = 0; q < 4; q++) s[q] += __shfl_xor_sync(0xffffffffu, s[q], o);
    float n[4];
    #pragma unroll
    for (int q = 0; q < 4; q++) {
        float inv = 1.0f / s[q];
        float p0 = e0[q] * inv, p1 = e1[q] * inv;
        ((__half2*)dst)[(size_t)(r0 + q) * 32 + lane] = __floats2half2_rn(p0, p1);
        n[q] = p0 * p0 + p1 * p1;
    }
    #pragma unroll
    for (int o = 16; o; o >>= 1)
        #pragma unroll
        for (int q = 0; q < 4; q++) n[q] += __shfl_xor_sync(0xffffffffu, n[q], o);
    if (lane == 0)
        #pragma unroll
        for (int q = 0; q < 4; q++) nrm[r0 + q] = n[q];
}

// ---------------- cost kernel: HMMA + fused exp -> fp16 K -----------------
// CTA: 256 thr (8 warps 4x2), tile M=128 x N=64, Kdepth=64.
__global__ __launch_bounds__(256) void cost_kernel() {
    __shared__ __half As[128][72];
    __shared__ __half Bs[64][72];
    __shared__ float  ys2[64];
    const int tid = threadIdx.x, warp = tid >> 5, lane = tid & 31;
    const int jt = blockIdx.x, it = blockIdx.y, b = blockIdx.z;
    const int i_base = (b << 10) + (it << 7);
    const int j_base = (b << 10) + (jt << 6);

    #pragma unroll
    for (int q = 0; q < 4; q++) {
        int idx = tid + (q << 8);
        int r = idx >> 3, ch = idx & 7;
        *(uint4*)&As[r][ch << 3] = ((const uint4*)(g_sxh + (size_t)(i_base + r) * D_))[ch];
    }
    #pragma unroll
    for (int q = 0; q < 2; q++) {
        int idx = tid + (q << 8);
        int r = idx >> 3, ch = idx & 7;
        *(uint4*)&Bs[r][ch << 3] = ((const uint4*)(g_syh + (size_t)(j_base + r) * D_))[ch];
    }
    if (tid < 64) ys2[tid] = g_y2[j_base + tid];
    __syncthreads();

    const int wr = warp & 3, wc = warp >> 2;
    const int m0 = wr << 5, n0 = wc << 5;

    float acc[2][4][4];
    #pragma unroll
    for (int mt = 0; mt < 2; mt++)
        #pragma unroll
        for (int nt = 0; nt < 4; nt++)
            #pragma unroll
            for (int e = 0; e < 4; e++) acc[mt][nt][e] = 0.f;

    #pragma unroll
    for (int ks = 0; ks < 4; ks++) {
        const int k0 = ks << 4;
        uint32_t af[2][4], bf[4][2];
        #pragma unroll
        for (int mt = 0; mt < 2; mt++) {
            uint32_t addr = smem_u32(&As[m0 + (mt << 4) + (lane & 15)][k0 + ((lane >> 4) << 3)]);
            ldsm_x4(af[mt][0], af[mt][1], af[mt][2], af[mt][3], addr);
        }
        #pragma unroll
        for (int np = 0; np < 2; np++) {
            int mat = lane >> 3, rin = lane & 7;
            int row = n0 + (np << 4) + ((mat >> 1) << 3) + rin;
            int col = k0 + ((mat & 1) << 3);
            uint32_t addr = smem_u32(&Bs[row][col]);
            uint32_t r0, r1, r2, r3;
            ldsm_x4(r0, r1, r2, r3, addr);
            bf[np * 2][0] = r0; bf[np * 2][1] = r1;
            bf[np * 2 + 1][0] = r2; bf[np * 2 + 1][1] = r3;
        }
        #pragma unroll
        for (int mt = 0; mt < 2; mt++)
            #pragma unroll
            for (int nt = 0; nt < 4; nt++)
                mma16816(acc[mt][nt], af[mt], bf[nt]);
    }

    // epilogue: C = x2 + y2 - 2s ; K = exp(-10C) -> fp16
    const int g = lane >> 2, tq = lane & 3;
    #pragma unroll
    for (int mt = 0; mt < 2; mt++) {
        int gi0 = i_base + m0 + (mt << 4) + g;
        int gi1 = gi0 + 8;
        float xi0 = g_x2[gi0], xi1 = g_x2[gi1];
        __half* d0 = g_Kh + ((size_t)gi0 << 10) + (jt << 6);
        __half* d1 = g_Kh + ((size_t)gi1 << 10) + (jt << 6);
        #pragma unroll
        for (int nt = 0; nt < 4; nt++) {
            int jl = n0 + (nt << 3) + (tq << 1);
            float yj0 = ys2[jl], yj1 = ys2[jl + 1];
            float c00 = xi0 + yj0 - 2.0f * acc[mt][nt][0];
            float c01 = xi0 + yj1 - 2.0f * acc[mt][nt][1];
            float c10 = xi1 + yj0 - 2.0f * acc[mt][nt][2];
            float c11 = xi1 + yj1 - 2.0f * acc[mt][nt][3];
            *(__half2*)(d0 + jl) = __floats2half2_rn(__expf(-10.0f * c00), __expf(-10.0f * c01));
            *(__half2*)(d1 + jl) = __floats2half2_rn(__expf(-10.0f * c10), __expf(-10.0f * c11));
        }
    }
}

// ---------------- flag-array grid barrier (low latency, no atomics) -------
__device__ __forceinline__ void grid_sync(unsigned tgt) {
    __syncthreads();
    if (blockIdx.x == 0) {
        if (threadIdx.x > 0 && threadIdx.x < NBLK) {
            while (((volatile unsigned*)g_flags)[threadIdx.x * BAR_STRIDE] < tgt) { }
        }
        __threadfence();
        __syncthreads();
        if (threadIdx.x == 0) *(volatile unsigned*)&g_gen2 = tgt;
        __syncthreads();
    } else {
        if (threadIdx.x == 0) {
            __threadfence();
            ((volatile unsigned*)g_flags)[blockIdx.x * BAR_STRIDE] = tgt;
            while (*(volatile unsigned*)&g_gen2 < tgt) { }
            __threadfence();
        }
        __syncthreads();
    }
}

// ---------------- persistent Sinkhorn: fused single-sweep iterations ------
__global__ __launch_bounds__(NTHR, 1) void sinkhorn_kernel(float* __restrict__ out) {
    __shared__ __align__(16) float sb_b[2048];     // staged b (1-2 batches)
    __shared__ float a_loc[128];                   // block-local a (scaling)
    __shared__ float red[1024];
    const int tid = threadIdx.x, blk = blockIdx.x;
    const int lane = tid & 31, warp = tid >> 5;
    const float mu = 1.0f / 1024.0f + 1e-8f;
    const float log_mu = logf(mu);

    unsigned bar = *(volatile unsigned*)&g_gen2;   // stable pre-launch value

    const int rs = blk * CHUNK;
    const int re = min(rs + CHUNK, TOTAL_ROWS);
    const int nrows = re - rs;
    const int b0 = rs >> 10;
    const int nslot = ((re - 1) >> 10) - b0 + 1;   // 1 or 2 batches spanned

    if (tid < 128) a_loc[tid] = 1.0f;
    if (blk < 16) g_b[(blk << 10) + tid] = 1.0f;
    if (blk == 0 && tid == 0) g_stop = 0;
    grid_sync(++bar);

    const int bslot = warp >> 4;                         // phase-B slot owner
    const int jc   = ((warp & 15) << 6) + (lane << 1);   // phase-B column (2/lane)
    const bool bact = warp < (nslot << 4);

    for (int it = 0; it < 100; ++it) {
        // stage b for this block's batches
        for (int idx = tid; idx < (nslot << 10); idx += NTHR)
            sb_b[idx] = __ldcg(&g_b[(b0 << 10) + idx]);
        __syncthreads();

        float t0 = 0.f, t1 = 0.f;
        for (int g0 = 0; g0 < nrows; g0 += 32) {
            // ---- phase A: warp w dots row g0+w: s = K_row . b ; update a ----
            int lr = g0 + warp;
            if (lr < nrows) {
                int r = rs + lr;
                const uint4* Kr = (const uint4*)(g_Kh + ((size_t)r << 10));
                const float* bs = sb_b + (((r >> 10) - b0) << 10);
                float aA = 0.f, aB = 0.f;
                #pragma unroll
                for (int k = 0; k < 4; k++) {
                    int u = lane + (k << 5);
                    uint4 v = Kr[u];
                    const float4* bp = (const float4*)(bs + (u << 3));
                    float4 q0 = bp[0], q1 = bp[1];
                    float2 f0 = __half22float2(*(__half2*)&v.x);
                    float2 f1 = __half22float2(*(__half2*)&v.y);
                    float2 f2 = __half22float2(*(__half2*)&v.z);
                    float2 f3 = __half22float2(*(__half2*)&v.w);
                    aA = fmaf(f0.x, q0.x, fmaf(f0.y, q0.y, fmaf(f1.x, q0.z, fmaf(f1.y, q0.w, aA))));
                    aB = fmaf(f2.x, q1.x, fmaf(f2.y, q1.y, fmaf(f3.x, q1.z, fmaf(f3.y, q1.w, aB))));
                }
                float acc = aA + aB;
                #pragma unroll
                for (int o = 16; o; o >>= 1) acc += __shfl_xor_sync(0xffffffffu, acc, o);
                if (lane == 0) {
                    float aold = a_loc[lr];
                    float as = fmaf(aold, acc, 1e-6f);
                    float du = EPS_ * (log_mu - __logf(as));
                    __stcg(&g_du[rs + lr], fabsf(du));
                    a_loc[lr] = mu * aold / as;
                }
            }
            __syncthreads();
            // ---- phase B: column strips from L1-hot rows: t_j += a_new*K[r][j] --
            if (bact) {
                int lim = min(g0 + 32, nrows);
                for (int lr2 = g0; lr2 < lim; lr2++) {
                    int r2 = rs + lr2;
                    if (((r2 >> 10) - b0) == bslot) {
                        uint32_t kk = *(const uint32_t*)(g_Kh + ((size_t)r2 << 10) + jc);
                        float2 kf = __half22float2(*(__half2*)&kk);
                        float av = a_loc[lr2];
                        t0 = fmaf(kf.x, av, t0);
                        t1 = fmaf(kf.y, av, t1);
                    }
                }
            }
        }
        if (bact) {
            float2 w2; w2.x = t0; w2.y = t1;
            *(float2*)&g_tp[blk * 2048 + (bslot << 10) + jc] = w2;
        }
        grid_sync(++bar);

        // ---- update step: blocks 0..15 reduce partials -> b ; block 16 err ---
        if (blk < 16) {
            int bb = blk, j = tid;
            int first = (bb << 10) / CHUNK;
            int last  = min(((bb << 10) + 1023) / CHUNK, NBLK - 1);
            float t = 0.f;
            for (int b2 = first; b2 <= last; b2++) {
                int bb0 = (b2 * CHUNK) >> 10;
                t += __ldcg(&g_tp[b2 * 2048 + ((bb - bb0) << 10) + j]);
            }
            float bold = __ldcg(&g_b[(bb << 10) + j]);
            float bt = fmaf(bold, t, 1e-6f);
            __stcg(&g_b[(bb << 10) + j], mu * bold / bt);
        } else if (blk == 16) {
            float s = 0.f;
            #pragma unroll
            for (int k = 0; k < 16; k++) s += __ldcg(&g_du[tid + (k << 10)]);
            red[tid] = s;
            __syncthreads();
            for (int off = 512; off; off >>= 1) {
                if (tid < off) red[tid] += red[tid + off];
                __syncthreads();
            }
            if (tid == 0) g_stop = (red[0] * (1.0f / 16.0f) < 0.1f) ? 1 : 0;
        }
        grid_sync(++bar);
        if (*((volatile int*)&g_stop)) break;
    }

    // ---- final: cost = -eps/16 * sum_r a_r * sum_j (K ln K) b_j ----
    for (int idx = tid; idx < (nslot << 10); idx += NTHR)
        sb_b[idx] = __ldcg(&g_b[(b0 << 10) + idx]);
    __syncthreads();
    for (int lr = warp; lr < nrows; lr += 32) {
        int r = rs + lr;
        const float* bs = sb_b + (((r >> 10) - b0) << 10);
        const uint4* Kr = (const uint4*)(g_Kh + ((size_t)r << 10));
        float acc = 0.f;
        #pragma unroll
        for (int k = 0; k < 4; k++) {
            int u = lane + (k << 5);
            uint4 v = Kr[u];
            const float4* bp = (const float4*)(bs + (u << 3));
            float4 q0 = bp[0], q1 = bp[1];
            float2 f0 = __half22float2(*(__half2*)&v.x);
            float2 f1 = __half22float2(*(__half2*)&v.y);
            float2 f2 = __half22float2(*(__half2*)&v.z);
            float2 f3 = __half22float2(*(__half2*)&v.w);
            float t0 = (f0.x > 0.f) ? f0.x * __logf(f0.x) : 0.f;
            float t1 = (f0.y > 0.f) ? f0.y * __logf(f0.y) : 0.f;
            float t2 = (f1.x > 0.f) ? f1.x * __logf(f1.x) : 0.f;
            float t3 = (f1.y > 0.f) ? f1.y * __logf(f1.y) : 0.f;
            float t4 = (f2.x > 0.f) ? f2.x * __logf(f2.x) : 0.f;
            float t5 = (f2.y > 0.f) ? f2.y * __logf(f2.y) : 0.f;
            float t6 = (f3.x > 0.f) ? f3.x * __logf(f3.x) : 0.f;
            float t7 = (f3.y > 0.f) ? f3.y * __logf(f3.y) : 0.f;
            acc = fmaf(t0, q0.x, fmaf(t1, q0.y, fmaf(t2, q0.z, fmaf(t3, q0.w, acc))));
            acc = fmaf(t4, q1.x, fmaf(t5, q1.y, fmaf(t6, q1.z, fmaf(t7, q1.w, acc))));
        }
        #pragma unroll
        for (int o = 16; o; o >>= 1) acc += __shfl_xor_sync(0xffffffffu, acc, o);
        if (lane == 0)
            __stcg(&g_du[r], a_loc[lr] * acc);
    }
    grid_sync(++bar);
    if (blk == 0) {
        float s = 0.f;
        #pragma unroll
        for (int k = 0; k < 16; k++) s += __ldcg(&g_du[tid + (k << 10)]);
        red[tid] = s;
        __syncthreads();
        for (int off = 512; off; off >>= 1) {
            if (tid < off) red[tid] += red[tid + off];
            __syncthreads();
        }
        if (tid == 0) out[0] = red[0] * (-EPS_ / 16.0f);
    }
}

// ---------------- launch ----------------
extern "C" void kernel_launch(void* const* d_in, const int* in_sizes, int n_in,
                              void* d_out, int out_size) {
    const float* x = (const float*)d_in[0];
    const float* y = (const float*)d_in[1];
    (void)in_sizes; (void)n_in; (void)out_size;

    softmax_kernel<<<1024, 256>>>(x, y);
    dim3 gc(16, 8, 16);   // (j-tiles of 64, i-tiles of 128, batch)
    cost_kernel<<<gc, 256>>>();
    sinkhorn_kernel<<<NBLK, NTHR>>>((float*)d_out);
}

// round 9
// speedup vs baseline: 1.2959x; 1.0992x over previous
#include <cuda_runtime.h>
#include <cuda_fp16.h>
#include <math.h>
#include <stdint.h>

// ---------------- problem constants ----------------
#define B_  16
#define N_  1024
#define D_  64
#define EPS_ 0.1f
#define TOTAL_ROWS (B_*N_)        // 16384
#define NBLK 148
#define NTHR 1024
#define BAR_STRIDE 32             // 128B between barrier flags

// ---------------- device scratch (static, no allocs) ----------------
__device__ __half g_sxh[TOTAL_ROWS*D_];            // softmax(x) fp16  2MB
__device__ __half g_syh[TOTAL_ROWS*D_];            // softmax(y) fp16  2MB
__device__ float  g_x2[TOTAL_ROWS];
__device__ float  g_y2[TOTAL_ROWS];
__device__ __half g_Kh[(size_t)B_*N_*N_];          // K = exp(-10C) fp16, 32MB
__device__ float  g_a[TOTAL_ROWS];
__device__ float  g_b[TOTAL_ROWS];
__device__ float  g_du[TOTAL_ROWS];
__device__ unsigned g_flags[NBLK*BAR_STRIDE];      // barrier flags (monotonic)
__device__ unsigned g_gen2;                        // barrier generation
__device__ int g_stop;

// ---------------- helpers ----------------
__device__ __forceinline__ uint32_t smem_u32(const void* p) {
    uint32_t a;
    asm("{ .reg .u64 t; cvta.to.shared.u64 t, %1; cvt.u32.u64 %0, t; }" : "=r"(a) : "l"(p));
    return a;
}
__device__ __forceinline__ void ldsm_x4(uint32_t& r0, uint32_t& r1, uint32_t& r2, uint32_t& r3,
                                        uint32_t addr) {
    asm volatile("ldmatrix.sync.aligned.m8n8.x4.shared.b16 {%0,%1,%2,%3}, [%4];"
                 : "=r"(r0), "=r"(r1), "=r"(r2), "=r"(r3) : "r"(addr));
}
__device__ __forceinline__ void mma16816(float* c, const uint32_t* a, const uint32_t* b) {
    asm volatile(
        "mma.sync.aligned.m16n8k16.row.col.f32.f16.f16.f32 "
        "{%0,%1,%2,%3}, {%4,%5,%6,%7}, {%8,%9}, {%0,%1,%2,%3};"
        : "+f"(c[0]), "+f"(c[1]), "+f"(c[2]), "+f"(c[3])
        : "r"(a[0]), "r"(a[1]), "r"(a[2]), "r"(a[3]), "r"(b[0]), "r"(b[1]));
}

// ---------------- softmax: 4 rows/warp, no-max-sub, fused e/e^2 tree ------
__global__ __launch_bounds__(256) void softmax_kernel(const float* __restrict__ x,
                                                      const float* __restrict__ y) {
    int w    = (blockIdx.x * blockDim.x + threadIdx.x) >> 5;   // 0..8191
    int lane = threadIdx.x & 31;
    const float* src; __half* dst; float* nrm; int r0;
    if (w < 4096) { src = x; dst = g_sxh; nrm = g_x2; r0 = w << 2; }
    else          { src = y; dst = g_syh; nrm = g_y2; r0 = (w - 4096) << 2; }
    float2 v[4];
    #pragma unroll
    for (int q = 0; q < 4; q++)
        v[q] = ((const float2*)(src + (size_t)(r0 + q) * D_))[lane];
    float e0[4], e1[4], s[4], n[4];
    #pragma unroll
    for (int q = 0; q < 4; q++) {
        e0[q] = __expf(v[q].x);
        e1[q] = __expf(v[q].y);
        s[q] = e0[q] + e1[q];
        n[q] = fmaf(e0[q], e0[q], e1[q] * e1[q]);
    }
    #pragma unroll
    for (int o = 16; o; o >>= 1)
        #pragma unroll
        for (int q = 0; q < 4; q++) {
            s[q] += __shfl_xor_sync(0xffffffffu, s[q], o);
            n[q] += __shfl_xor_sync(0xffffffffu, n[q], o);
        }
    #pragma unroll
    for (int q = 0; q < 4; q++) {
        float inv = 1.0f / s[q];
        ((__half2*)dst)[(size_t)(r0 + q) * 32 + lane] =
            __floats2half2_rn(e0[q] * inv, e1[q] * inv);
    }
    if (lane == 0)
        #pragma unroll
        for (int q = 0; q < 4; q++) nrm[r0 + q] = n[q] / (s[q] * s[q]);
}

// ---------------- cost kernel: HMMA + fused exp -> fp16 K -----------------
// CTA: 256 thr (8 warps 4x2), tile M=128 x N=64, Kdepth=64.
__global__ __launch_bounds__(256) void cost_kernel() {
    __shared__ __half As[128][72];
    __shared__ __half Bs[64][72];
    __shared__ float  ys2[64];
    const int tid = threadIdx.x, warp = tid >> 5, lane = tid & 31;
    const int jt = blockIdx.x, it = blockIdx.y, b = blockIdx.z;
    const int i_base = (b << 10) + (it << 7);
    const int j_base = (b << 10) + (jt << 6);

    #pragma unroll
    for (int q = 0; q < 4; q++) {
        int idx = tid + (q << 8);
        int r = idx >> 3, ch = idx & 7;
        *(uint4*)&As[r][ch << 3] = ((const uint4*)(g_sxh + (size_t)(i_base + r) * D_))[ch];
    }
    #pragma unroll
    for (int q = 0; q < 2; q++) {
        int idx = tid + (q << 8);
        int r = idx >> 3, ch = idx & 7;
        *(uint4*)&Bs[r][ch << 3] = ((const uint4*)(g_syh + (size_t)(j_base + r) * D_))[ch];
    }
    if (tid < 64) ys2[tid] = g_y2[j_base + tid];
    __syncthreads();

    const int wr = warp & 3, wc = warp >> 2;
    const int m0 = wr << 5, n0 = wc << 5;

    float acc[2][4][4];
    #pragma unroll
    for (int mt = 0; mt < 2; mt++)
        #pragma unroll
        for (int nt = 0; nt < 4; nt++)
            #pragma unroll
            for (int e = 0; e < 4; e++) acc[mt][nt][e] = 0.f;

    #pragma unroll
    for (int ks = 0; ks < 4; ks++) {
        const int k0 = ks << 4;
        uint32_t af[2][4], bf[4][2];
        #pragma unroll
        for (int mt = 0; mt < 2; mt++) {
            uint32_t addr = smem_u32(&As[m0 + (mt << 4) + (lane & 15)][k0 + ((lane >> 4) << 3)]);
            ldsm_x4(af[mt][0], af[mt][1], af[mt][2], af[mt][3], addr);
        }
        #pragma unroll
        for (int np = 0; np < 2; np++) {
            int mat = lane >> 3, rin = lane & 7;
            int row = n0 + (np << 4) + ((mat >> 1) << 3) + rin;
            int col = k0 + ((mat & 1) << 3);
            uint32_t addr = smem_u32(&Bs[row][col]);
            uint32_t r0, r1, r2, r3;
            ldsm_x4(r0, r1, r2, r3, addr);
            bf[np * 2][0] = r0; bf[np * 2][1] = r1;
            bf[np * 2 + 1][0] = r2; bf[np * 2 + 1][1] = r3;
        }
        #pragma unroll
        for (int mt = 0; mt < 2; mt++)
            #pragma unroll
            for (int nt = 0; nt < 4; nt++)
                mma16816(acc[mt][nt], af[mt], bf[nt]);
    }

    // epilogue: C = x2 + y2 - 2s ; K = exp(-10C) -> fp16
    const int g = lane >> 2, tq = lane & 3;
    #pragma unroll
    for (int mt = 0; mt < 2; mt++) {
        int gi0 = i_base + m0 + (mt << 4) + g;
        int gi1 = gi0 + 8;
        float xi0 = g_x2[gi0], xi1 = g_x2[gi1];
        __half* d0 = g_Kh + ((size_t)gi0 << 10) + (jt << 6);
        __half* d1 = g_Kh + ((size_t)gi1 << 10) + (jt << 6);
        #pragma unroll
        for (int nt = 0; nt < 4; nt++) {
            int jl = n0 + (nt << 3) + (tq << 1);
            float yj0 = ys2[jl], yj1 = ys2[jl + 1];
            float c00 = xi0 + yj0 - 2.0f * acc[mt][nt][0];
            float c01 = xi0 + yj1 - 2.0f * acc[mt][nt][1];
            float c10 = xi1 + yj0 - 2.0f * acc[mt][nt][2];
            float c11 = xi1 + yj1 - 2.0f * acc[mt][nt][3];
            *(__half2*)(d0 + jl) = __floats2half2_rn(__expf(-10.0f * c00), __expf(-10.0f * c01));
            *(__half2*)(d1 + jl) = __floats2half2_rn(__expf(-10.0f * c10), __expf(-10.0f * c11));
        }
    }
}

// ---------------- flag-array grid barrier (no contended atomics) ----------
__device__ __forceinline__ void grid_sync(unsigned tgt) {
    __syncthreads();
    if (blockIdx.x == 0) {
        if (threadIdx.x > 0 && threadIdx.x < NBLK) {
            while (((volatile unsigned*)g_flags)[threadIdx.x * BAR_STRIDE] < tgt) { }
        }
        __threadfence();
        __syncthreads();
        if (threadIdx.x == 0) *(volatile unsigned*)&g_gen2 = tgt;
        __syncthreads();
    } else {
        if (threadIdx.x == 0) {
            __threadfence();
            ((volatile unsigned*)g_flags)[blockIdx.x * BAR_STRIDE] = tgt;
            while (*(volatile unsigned*)&g_gen2 < tgt) { }
            __threadfence();
        }
        __syncthreads();
    }
}

// ---------------- persistent Sinkhorn loop + final cost (R4 structure) ----
__global__ __launch_bounds__(NTHR, 1) void sinkhorn_kernel(float* __restrict__ out) {
    __shared__ __align__(16) float sbuf[9216];
    const int tid = threadIdx.x, blk = blockIdx.x;
    const int lane = tid & 31, warp = tid >> 5;
    const float mu = 1.0f / 1024.0f + 1e-8f;
    const float log_mu = logf(mu);

    unsigned bar = *(volatile unsigned*)&g_gen2;   // stable pre-launch value

    {
        int gg = blk * NTHR + tid;
        if (gg < TOTAL_ROWS) { g_a[gg] = 1.0f; g_b[gg] = 1.0f; }
        if (blk == 0 && tid == 0) g_stop = 0;
    }
    grid_sync(++bar);

    const int chunk = (TOTAL_ROWS + NBLK - 1) / NBLK;   // 111
    const int rs = blk * chunk;
    const int re = min(rs + chunk, TOTAL_ROWS);
    const int b0 = rs >> 10;
    const int nstage = (rs < re) ? ((((re - 1) >> 10) - b0 + 1) << 10) : 0;

    for (int it = 0; it < 100; ++it) {
        // ---- row pass: s_i = sum_j K_ij b_j ; update a, |du| ----
        if (rs < re) {
            for (int idx = tid; idx < nstage; idx += NTHR)
                sbuf[idx] = __ldcg(&g_b[(b0 << 10) + idx]);
            __syncthreads();
            for (int r = rs + warp; r < re; r += 32) {
                const float* bs = sbuf + (((r >> 10) - b0) << 10);
                const uint4* Kr = (const uint4*)(g_Kh + ((size_t)r << 10));
                float acc = 0.f;
                #pragma unroll
                for (int k = 0; k < 4; k++) {
                    int u = lane + (k << 5);
                    uint4 v = Kr[u];
                    const float4* bp = (const float4*)(bs + (u << 3));
                    float4 q0 = bp[0], q1 = bp[1];
                    float2 f0 = __half22float2(*(__half2*)&v.x);
                    float2 f1 = __half22float2(*(__half2*)&v.y);
                    float2 f2 = __half22float2(*(__half2*)&v.z);
                    float2 f3 = __half22float2(*(__half2*)&v.w);
                    acc = fmaf(f0.x, q0.x, fmaf(f0.y, q0.y, fmaf(f1.x, q0.z, fmaf(f1.y, q0.w, acc))));
                    acc = fmaf(f2.x, q1.x, fmaf(f2.y, q1.y, fmaf(f3.x, q1.z, fmaf(f3.y, q1.w, acc))));
                }
                #pragma unroll
                for (int o = 16; o; o >>= 1) acc += __shfl_xor_sync(0xffffffffu, acc, o);
                if (lane == 0) {
                    float aold = __ldcg(&g_a[r]);
                    float as = fmaf(aold, acc, 1e-6f);
                    float du = EPS_ * (log_mu - __logf(as));
                    __stcg(&g_a[r], mu * aold / as);
                    __stcg(&g_du[r], fabsf(du));
                }
            }
        }
        grid_sync(++bar);
        // ---- col pass (blocks 0..127): t_j = sum_i K_ij a_i ; update b ----
        if (blk < 128) {
            int bb = blk >> 3, j0 = (blk & 7) << 7;
            sbuf[tid] = __ldcg(&g_a[(bb << 10) + tid]);
            __syncthreads();
            int jc = tid & 15, ig = tid >> 4;       // 16 uint4-strips x 64 i-groups
            float acc[8] = {0.f,0.f,0.f,0.f,0.f,0.f,0.f,0.f};
            const unsigned char* base = (const unsigned char*)g_Kh
                                        + (((size_t)bb << 20) + j0 + (jc << 3)) * 2;
            #pragma unroll 4
            for (int i = ig; i < 1024; i += 64) {
                uint4 v = *(const uint4*)(base + ((size_t)i << 11));
                float ai = sbuf[i];
                float2 f0 = __half22float2(*(__half2*)&v.x);
                float2 f1 = __half22float2(*(__half2*)&v.y);
                float2 f2 = __half22float2(*(__half2*)&v.z);
                float2 f3 = __half22float2(*(__half2*)&v.w);
                acc[0] = fmaf(f0.x, ai, acc[0]); acc[1] = fmaf(f0.y, ai, acc[1]);
                acc[2] = fmaf(f1.x, ai, acc[2]); acc[3] = fmaf(f1.y, ai, acc[3]);
                acc[4] = fmaf(f2.x, ai, acc[4]); acc[5] = fmaf(f2.y, ai, acc[5]);
                acc[6] = fmaf(f3.x, ai, acc[6]); acc[7] = fmaf(f3.y, ai, acc[7]);
            }
            float* sred = sbuf + 1024;
            *(float4*)(sred + (ig << 7) + (jc << 3))     = make_float4(acc[0], acc[1], acc[2], acc[3]);
            *(float4*)(sred + (ig << 7) + (jc << 3) + 4) = make_float4(acc[4], acc[5], acc[6], acc[7]);
            __syncthreads();
            if (tid < 128) {
                float t = 0.f;
                #pragma unroll
                for (int g = 0; g < 64; g++) t += sred[(g << 7) + tid];
                int j = (bb << 10) + j0 + tid;
                float bold = __ldcg(&g_b[j]);
                float bt = fmaf(bold, t, 1e-6f);
                __stcg(&g_b[j], mu * bold / bt);
            }
        } else if (blk == 128) {
            float s = 0.f;
            #pragma unroll
            for (int k = 0; k < 16; k++) s += __ldcg(&g_du[tid + (k << 10)]);
            sbuf[tid] = s;
            __syncthreads();
            for (int off = 512; off; off >>= 1) {
                if (tid < off) sbuf[tid] += sbuf[tid + off];
                __syncthreads();
            }
            if (tid == 0) g_stop = (sbuf[0] * (1.0f / 16.0f) < 0.1f) ? 1 : 0;
        }
        grid_sync(++bar);
        if (*((volatile int*)&g_stop)) break;
    }

    // ---- final: cost = -eps/16 * sum_r a_r * sum_j (K ln K) b_j ----
    if (rs < re) {
        __syncthreads();
        for (int idx = tid; idx < nstage; idx += NTHR)
            sbuf[idx] = __ldcg(&g_b[(b0 << 10) + idx]);
        __syncthreads();
        for (int r = rs + warp; r < re; r += 32) {
            const float* bs = sbuf + (((r >> 10) - b0) << 10);
            const uint4* Kr = (const uint4*)(g_Kh + ((size_t)r << 10));
            float acc = 0.f;
            #pragma unroll
            for (int k = 0; k < 4; k++) {
                int u = lane + (k << 5);
                uint4 v = Kr[u];
                const float4* bp = (const float4*)(bs + (u << 3));
                float4 q0 = bp[0], q1 = bp[1];
                float2 f0 = __half22float2(*(__half2*)&v.x);
                float2 f1 = __half22float2(*(__half2*)&v.y);
                float2 f2 = __half22float2(*(__half2*)&v.z);
                float2 f3 = __half22float2(*(__half2*)&v.w);
                float t0 = (f0.x > 0.f) ? f0.x * __logf(f0.x) : 0.f;
                float t1 = (f0.y > 0.f) ? f0.y * __logf(f0.y) : 0.f;
                float t2 = (f1.x > 0.f) ? f1.x * __logf(f1.x) : 0.f;
                float t3 = (f1.y > 0.f) ? f1.y * __logf(f1.y) : 0.f;
                float t4 = (f2.x > 0.f) ? f2.x * __logf(f2.x) : 0.f;
                float t5 = (f2.y > 0.f) ? f2.y * __logf(f2.y) : 0.f;
                float t6 = (f3.x > 0.f) ? f3.x * __logf(f3.x) : 0.f;
                float t7 = (f3.y > 0.f) ? f3.y * __logf(f3.y) : 0.f;
                acc = fmaf(t0, q0.x, fmaf(t1, q0.y, fmaf(t2, q0.z, fmaf(t3, q0.w, acc))));
                acc = fmaf(t4, q1.x, fmaf(t5, q1.y, fmaf(t6, q1.z, fmaf(t7, q1.w, acc))));
            }
            #pragma unroll
            for (int o = 16; o; o >>= 1) acc += __shfl_xor_sync(0xffffffffu, acc, o);
            if (lane == 0)
                __stcg(&g_du[r], __ldcg(&g_a[r]) * acc);
        }
    }
    grid_sync(++bar);
    if (blk == 0) {
        float s = 0.f;
        #pragma unroll
        for (int k = 0; k < 16; k++) s += __ldcg(&g_du[tid + (k << 10)]);
        sbuf[tid] = s;
        __syncthreads();
        for (int off = 512; off; off >>= 1) {
            if (tid < off) sbuf[tid] += sbuf[tid + off];
            __syncthreads();
        }
        if (tid == 0) out[0] = sbuf[0] * (-EPS_ / 16.0f);
    }
}

// ---------------- launch ----------------
extern "C" void kernel_launch(void* const* d_in, const int* in_sizes, int n_in,
                              void* d_out, int out_size) {
    const float* x = (const float*)d_in[0];
    const float* y = (const float*)d_in[1];
    (void)in_sizes; (void)n_in; (void)out_size;

    softmax_kernel<<<1024, 256>>>(x, y);
    dim3 gc(16, 8, 16);   // (j-tiles of 64, i-tiles of 128, batch)
    cost_kernel<<<gc, 256>>>();
    sinkhorn_kernel<<<NBLK, NTHR>>>((float*)d_out);
}

// round 10
// speedup vs baseline: 1.3052x; 1.0072x over previous
#include <cuda_runtime.h>
#include <cuda_fp16.h>
#include <math.h>
#include <stdint.h>

// ---------------- problem constants ----------------
#define B_  16
#define N_  1024
#define D_  64
#define EPS_ 0.1f
#define TOTAL_ROWS (B_*N_)        // 16384
#define NBLK 148
#define SKT 512                   // sinkhorn threads (16 warps)
#define CHUNK 111                 // ceil(16384/148)
#define BAR_STRIDE 32             // 128B between barrier flags
// dyn smem: sb_b 2048f + wp 16*1024f + red 512f
#define SK_SMEM_FLOATS (2048 + 16*1024 + 512)
#define SK_SMEM_BYTES  (SK_SMEM_FLOATS * 4)

// ---------------- device scratch (static, no allocs) ----------------
__device__ __half g_sxh[TOTAL_ROWS*D_];            // softmax(x) fp16  2MB
__device__ __half g_syh[TOTAL_ROWS*D_];            // softmax(y) fp16  2MB
__device__ float  g_x2[TOTAL_ROWS];
__device__ float  g_y2[TOTAL_ROWS];
__device__ __half g_Kh[(size_t)B_*N_*N_];          // K = exp(-10C) fp16, 32MB
__device__ float  g_b[TOTAL_ROWS];
__device__ float  g_du[TOTAL_ROWS];
__device__ float  g_tp[NBLK*2048];                 // per-block col partials (2 slots)
__device__ unsigned g_flags[NBLK*BAR_STRIDE];      // barrier flags (monotonic)
__device__ unsigned g_gen2;                        // barrier generation
__device__ int g_stop;

// ---------------- helpers ----------------
__device__ __forceinline__ uint32_t smem_u32(const void* p) {
    uint32_t a;
    asm("{ .reg .u64 t; cvta.to.shared.u64 t, %1; cvt.u32.u64 %0, t; }" : "=r"(a) : "l"(p));
    return a;
}
__device__ __forceinline__ void ldsm_x4(uint32_t& r0, uint32_t& r1, uint32_t& r2, uint32_t& r3,
                                        uint32_t addr) {
    asm volatile("ldmatrix.sync.aligned.m8n8.x4.shared.b16 {%0,%1,%2,%3}, [%4];"
                 : "=r"(r0), "=r"(r1), "=r"(r2), "=r"(r3) : "r"(addr));
}
__device__ __forceinline__ void mma16816(float* c, const uint32_t* a, const uint32_t* b) {
    asm volatile(
        "mma.sync.aligned.m16n8k16.row.col.f32.f16.f16.f32 "
        "{%0,%1,%2,%3}, {%4,%5,%6,%7}, {%8,%9}, {%0,%1,%2,%3};"
        : "+f"(c[0]), "+f"(c[1]), "+f"(c[2]), "+f"(c[3])
        : "r"(a[0]), "r"(a[1]), "r"(a[2]), "r"(a[3]), "r"(b[0]), "r"(b[1]));
}

// ---------------- softmax: 4 rows/warp, no-max-sub (R9) -------------------
__global__ __launch_bounds__(256) void softmax_kernel(const float* __restrict__ x,
                                                      const float* __restrict__ y) {
    int w    = (blockIdx.x * blockDim.x + threadIdx.x) >> 5;
    int lane = threadIdx.x & 31;
    const float* src; __half* dst; float* nrm; int r0;
    if (w < 4096) { src = x; dst = g_sxh; nrm = g_x2; r0 = w << 2; }
    else          { src = y; dst = g_syh; nrm = g_y2; r0 = (w - 4096) << 2; }
    float2 v[4];
    #pragma unroll
    for (int q = 0; q < 4; q++)
        v[q] = ((const float2*)(src + (size_t)(r0 + q) * D_))[lane];
    float e0[4], e1[4], s[4], n[4];
    #pragma unroll
    for (int q = 0; q < 4; q++) {
        e0[q] = __expf(v[q].x);
        e1[q] = __expf(v[q].y);
        s[q] = e0[q] + e1[q];
        n[q] = fmaf(e0[q], e0[q], e1[q] * e1[q]);
    }
    #pragma unroll
    for (int o = 16; o; o >>= 1)
        #pragma unroll
        for (int q = 0; q < 4; q++) {
            s[q] += __shfl_xor_sync(0xffffffffu, s[q], o);
            n[q] += __shfl_xor_sync(0xffffffffu, n[q], o);
        }
    #pragma unroll
    for (int q = 0; q < 4; q++) {
        float inv = 1.0f / s[q];
        ((__half2*)dst)[(size_t)(r0 + q) * 32 + lane] =
            __floats2half2_rn(e0[q] * inv, e1[q] * inv);
    }
    if (lane == 0)
        #pragma unroll
        for (int q = 0; q < 4; q++) nrm[r0 + q] = n[q] / (s[q] * s[q]);
}

// ---------------- cost kernel: HMMA + fused exp -> fp16 K (R4) ------------
__global__ __launch_bounds__(256) void cost_kernel() {
    __shared__ __half As[128][72];
    __shared__ __half Bs[64][72];
    __shared__ float  ys2[64];
    const int tid = threadIdx.x, warp = tid >> 5, lane = tid & 31;
    const int jt = blockIdx.x, it = blockIdx.y, b = blockIdx.z;
    const int i_base = (b << 10) + (it << 7);
    const int j_base = (b << 10) + (jt << 6);

    #pragma unroll
    for (int q = 0; q < 4; q++) {
        int idx = tid + (q << 8);
        int r = idx >> 3, ch = idx & 7;
        *(uint4*)&As[r][ch << 3] = ((const uint4*)(g_sxh + (size_t)(i_base + r) * D_))[ch];
    }
    #pragma unroll
    for (int q = 0; q < 2; q++) {
        int idx = tid + (q << 8);
        int r = idx >> 3, ch = idx & 7;
        *(uint4*)&Bs[r][ch << 3] = ((const uint4*)(g_syh + (size_t)(j_base + r) * D_))[ch];
    }
    if (tid < 64) ys2[tid] = g_y2[j_base + tid];
    __syncthreads();

    const int wr = warp & 3, wc = warp >> 2;
    const int m0 = wr << 5, n0 = wc << 5;

    float acc[2][4][4];
    #pragma unroll
    for (int mt = 0; mt < 2; mt++)
        #pragma unroll
        for (int nt = 0; nt < 4; nt++)
            #pragma unroll
            for (int e = 0; e < 4; e++) acc[mt][nt][e] = 0.f;

    #pragma unroll
    for (int ks = 0; ks < 4; ks++) {
        const int k0 = ks << 4;
        uint32_t af[2][4], bf[4][2];
        #pragma unroll
        for (int mt = 0; mt < 2; mt++) {
            uint32_t addr = smem_u32(&As[m0 + (mt << 4) + (lane & 15)][k0 + ((lane >> 4) << 3)]);
            ldsm_x4(af[mt][0], af[mt][1], af[mt][2], af[mt][3], addr);
        }
        #pragma unroll
        for (int np = 0; np < 2; np++) {
            int mat = lane >> 3, rin = lane & 7;
            int row = n0 + (np << 4) + ((mat >> 1) << 3) + rin;
            int col = k0 + ((mat & 1) << 3);
            uint32_t addr = smem_u32(&Bs[row][col]);
            uint32_t r0, r1, r2, r3;
            ldsm_x4(r0, r1, r2, r3, addr);
            bf[np * 2][0] = r0; bf[np * 2][1] = r1;
            bf[np * 2 + 1][0] = r2; bf[np * 2 + 1][1] = r3;
        }
        #pragma unroll
        for (int mt = 0; mt < 2; mt++)
            #pragma unroll
            for (int nt = 0; nt < 4; nt++)
                mma16816(acc[mt][nt], af[mt], bf[nt]);
    }

    const int g = lane >> 2, tq = lane & 3;
    #pragma unroll
    for (int mt = 0; mt < 2; mt++) {
        int gi0 = i_base + m0 + (mt << 4) + g;
        int gi1 = gi0 + 8;
        float xi0 = g_x2[gi0], xi1 = g_x2[gi1];
        __half* d0 = g_Kh + ((size_t)gi0 << 10) + (jt << 6);
        __half* d1 = g_Kh + ((size_t)gi1 << 10) + (jt << 6);
        #pragma unroll
        for (int nt = 0; nt < 4; nt++) {
            int jl = n0 + (nt << 3) + (tq << 1);
            float yj0 = ys2[jl], yj1 = ys2[jl + 1];
            float c00 = xi0 + yj0 - 2.0f * acc[mt][nt][0];
            float c01 = xi0 + yj1 - 2.0f * acc[mt][nt][1];
            float c10 = xi1 + yj0 - 2.0f * acc[mt][nt][2];
            float c11 = xi1 + yj1 - 2.0f * acc[mt][nt][3];
            *(__half2*)(d0 + jl) = __floats2half2_rn(__expf(-10.0f * c00), __expf(-10.0f * c01));
            *(__half2*)(d1 + jl) = __floats2half2_rn(__expf(-10.0f * c10), __expf(-10.0f * c11));
        }
    }
}

// ---------------- flag-array grid barrier ----------------
__device__ __forceinline__ void grid_sync(unsigned tgt) {
    __syncthreads();
    if (blockIdx.x == 0) {
        if (threadIdx.x > 0 && threadIdx.x < NBLK) {
            while (((volatile unsigned*)g_flags)[threadIdx.x * BAR_STRIDE] < tgt) { }
        }
        __threadfence();
        __syncthreads();
        if (threadIdx.x == 0) *(volatile unsigned*)&g_gen2 = tgt;
        __syncthreads();
    } else {
        if (threadIdx.x == 0) {
            __threadfence();
            ((volatile unsigned*)g_flags)[blockIdx.x * BAR_STRIDE] = tgt;
            while (*(volatile unsigned*)&g_gen2 < tgt) { }
            __threadfence();
        }
        __syncthreads();
    }
}

// ---------------- fused persistent Sinkhorn: ONE K sweep per iteration ----
// 512 thr (16 warps). Each warp: row pair -> dot with b (s_i), a-update,
// then immediate col accumulation a_new*K into 32 per-lane fp32 regs.
__global__ __launch_bounds__(SKT, 1) void sinkhorn_kernel(float* __restrict__ out) {
    extern __shared__ float sm[];
    float* sb_b = sm;                 // 2048
    float* wp   = sm + 2048;          // 16*1024 per-warp col partials
    float* red  = sm + 2048 + 16384;  // 512
    __shared__ float a_loc[128];
    const int tid = threadIdx.x, blk = blockIdx.x;
    const int lane = tid & 31, warp = tid >> 5;
    const float mu = 1.0f / 1024.0f + 1e-8f;
    const float log_mu = logf(mu);

    unsigned bar = *(volatile unsigned*)&g_gen2;

    const int rs = blk * CHUNK;
    const int re = min(rs + CHUNK, TOTAL_ROWS);
    const int nrows = re - rs;
    const int b0 = rs >> 10;
    const int nslot = ((re - 1) >> 10) - b0 + 1;   // 1 or 2

    if (tid < 128) a_loc[tid] = 1.0f;
    if (blk < 16)
        for (int j = tid; j < 1024; j += SKT) g_b[(blk << 10) + j] = 1.0f;
    if (blk == 0 && tid == 0) g_stop = 0;
    grid_sync(++bar);

    for (int it = 0; it < 100; ++it) {
        // stage b for this block's batch slots
        for (int idx = tid; idx < (nslot << 10); idx += SKT)
            sb_b[idx] = __ldcg(&g_b[(b0 << 10) + idx]);
        __syncthreads();

        for (int slot = 0; slot < nslot; ++slot) {
            const int seg_s = max(0, ((b0 + slot) << 10) - rs);
            const int seg_e = min(nrows, ((b0 + slot + 1) << 10) - rs);
            const float* bs = sb_b + (slot << 10);
            // hoist this lane's b values (32 floats, fixed cols across rows)
            float4 bq[8];
            #pragma unroll
            for (int k = 0; k < 4; k++) {
                const float* bp = bs + ((lane + (k << 5)) << 3);
                bq[k * 2]     = *(const float4*)bp;
                bq[k * 2 + 1] = *(const float4*)(bp + 4);
            }
            float ca[32];
            #pragma unroll
            for (int e = 0; e < 32; e++) ca[e] = 0.f;

            for (int lr = seg_s + warp; lr < seg_e; lr += 32) {
                const int lrB = lr + 16;
                const bool hasB = (lrB < seg_e);
                uint4 va[4], vb[4];
                const uint4* KA = (const uint4*)(g_Kh + ((size_t)(rs + lr) << 10));
                #pragma unroll
                for (int k = 0; k < 4; k++) va[k] = KA[lane + (k << 5)];
                if (hasB) {
                    const uint4* KB = (const uint4*)(g_Kh + ((size_t)(rs + lrB) << 10));
                    #pragma unroll
                    for (int k = 0; k < 4; k++) vb[k] = KB[lane + (k << 5)];
                }
                // ---- dot A (R4-identical chain order) ----
                float accA = 0.f;
                #pragma unroll
                for (int k = 0; k < 4; k++) {
                    float2 f0 = __half22float2(*(__half2*)&va[k].x);
                    float2 f1 = __half22float2(*(__half2*)&va[k].y);
                    float2 f2 = __half22float2(*(__half2*)&va[k].z);
                    float2 f3 = __half22float2(*(__half2*)&va[k].w);
                    float4 q0 = bq[k * 2], q1 = bq[k * 2 + 1];
                    accA = fmaf(f0.x, q0.x, fmaf(f0.y, q0.y, fmaf(f1.x, q0.z, fmaf(f1.y, q0.w, accA))));
                    accA = fmaf(f2.x, q1.x, fmaf(f2.y, q1.y, fmaf(f3.x, q1.z, fmaf(f3.y, q1.w, accA))));
                }
                float accB = 0.f;
                if (hasB) {
                    #pragma unroll
                    for (int k = 0; k < 4; k++) {
                        float2 f0 = __half22float2(*(__half2*)&vb[k].x);
                        float2 f1 = __half22float2(*(__half2*)&vb[k].y);
                        float2 f2 = __half22float2(*(__half2*)&vb[k].z);
                        float2 f3 = __half22float2(*(__half2*)&vb[k].w);
                        float4 q0 = bq[k * 2], q1 = bq[k * 2 + 1];
                        accB = fmaf(f0.x, q0.x, fmaf(f0.y, q0.y, fmaf(f1.x, q0.z, fmaf(f1.y, q0.w, accB))));
                        accB = fmaf(f2.x, q1.x, fmaf(f2.y, q1.y, fmaf(f3.x, q1.z, fmaf(f3.y, q1.w, accB))));
                    }
                }
                #pragma unroll
                for (int o = 16; o; o >>= 1) {
                    accA += __shfl_xor_sync(0xffffffffu, accA, o);
                    accB += __shfl_xor_sync(0xffffffffu, accB, o);
                }
                float aA = 0.f, aB = 0.f;
                if (lane == 0) {
                    float aold = a_loc[lr];
                    float as = fmaf(aold, accA, 1e-6f);
                    __stcg(&g_du[rs + lr], fabsf(EPS_ * (log_mu - __logf(as))));
                    aA = mu * aold / as;
                    a_loc[lr] = aA;
                    if (hasB) {
                        float bold = a_loc[lrB];
                        float bsv = fmaf(bold, accB, 1e-6f);
                        __stcg(&g_du[rs + lrB], fabsf(EPS_ * (log_mu - __logf(bsv))));
                        aB = mu * bold / bsv;
                        a_loc[lrB] = aB;
                    }
                }
                aA = __shfl_sync(0xffffffffu, aA, 0);
                aB = __shfl_sync(0xffffffffu, aB, 0);
                // ---- col accumulation from register-held K ----
                #pragma unroll
                for (int k = 0; k < 4; k++) {
                    float2 f0 = __half22float2(*(__half2*)&va[k].x);
                    float2 f1 = __half22float2(*(__half2*)&va[k].y);
                    float2 f2 = __half22float2(*(__half2*)&va[k].z);
                    float2 f3 = __half22float2(*(__half2*)&va[k].w);
                    ca[k*8+0] = fmaf(f0.x, aA, ca[k*8+0]); ca[k*8+1] = fmaf(f0.y, aA, ca[k*8+1]);
                    ca[k*8+2] = fmaf(f1.x, aA, ca[k*8+2]); ca[k*8+3] = fmaf(f1.y, aA, ca[k*8+3]);
                    ca[k*8+4] = fmaf(f2.x, aA, ca[k*8+4]); ca[k*8+5] = fmaf(f2.y, aA, ca[k*8+5]);
                    ca[k*8+6] = fmaf(f3.x, aA, ca[k*8+6]); ca[k*8+7] = fmaf(f3.y, aA, ca[k*8+7]);
                }
                if (hasB) {
                    #pragma unroll
                    for (int k = 0; k < 4; k++) {
                        float2 f0 = __half22float2(*(__half2*)&vb[k].x);
                        float2 f1 = __half22float2(*(__half2*)&vb[k].y);
                        float2 f2 = __half22float2(*(__half2*)&vb[k].z);
                        float2 f3 = __half22float2(*(__half2*)&vb[k].w);
                        ca[k*8+0] = fmaf(f0.x, aB, ca[k*8+0]); ca[k*8+1] = fmaf(f0.y, aB, ca[k*8+1]);
                        ca[k*8+2] = fmaf(f1.x, aB, ca[k*8+2]); ca[k*8+3] = fmaf(f1.y, aB, ca[k*8+3]);
                        ca[k*8+4] = fmaf(f2.x, aB, ca[k*8+4]); ca[k*8+5] = fmaf(f2.y, aB, ca[k*8+5]);
                        ca[k*8+6] = fmaf(f3.x, aB, ca[k*8+6]); ca[k*8+7] = fmaf(f3.y, aB, ca[k*8+7]);
                    }
                }
            }
            // ---- flush warp partials, reduce 16 warps -> g_tp[blk][slot] ----
            #pragma unroll
            for (int k = 0; k < 4; k++) {
                int cb = (lane + (k << 5)) << 3;
                *(float4*)&wp[(warp << 10) + cb]     = make_float4(ca[k*8+0], ca[k*8+1], ca[k*8+2], ca[k*8+3]);
                *(float4*)&wp[(warp << 10) + cb + 4] = make_float4(ca[k*8+4], ca[k*8+5], ca[k*8+6], ca[k*8+7]);
            }
            __syncthreads();
            for (int j = tid; j < 1024; j += SKT) {
                float t = 0.f;
                #pragma unroll
                for (int w = 0; w < 16; w++) t += wp[(w << 10) + j];
                __stcg(&g_tp[blk * 2048 + (slot << 10) + j], t);
            }
            __syncthreads();
        }
        grid_sync(++bar);

        // ---- b update (blocks 0..15, one batch each) ; err on block 16 ----
        if (blk < 16) {
            const int jf = (blk << 10) / CHUNK;
            const int jl = min(((blk << 10) + 1023) / CHUNK, NBLK - 1);
            for (int j = tid; j < 1024; j += SKT) {
                float t = 0.f;
                for (int q = jf; q <= jl; q++) {
                    int slot = blk - ((q * CHUNK) >> 10);
                    t += __ldcg(&g_tp[q * 2048 + (slot << 10) + j]);
                }
                int gj = (blk << 10) + j;
                float bold = __ldcg(&g_b[gj]);
                float bt = fmaf(bold, t, 1e-6f);
                __stcg(&g_b[gj], mu * bold / bt);
            }
        } else if (blk == 16) {
            float s = 0.f;
            #pragma unroll
            for (int k = 0; k < 32; k++) s += __ldcg(&g_du[tid + (k << 9)]);
            red[tid] = s;
            __syncthreads();
            for (int off = 256; off; off >>= 1) {
                if (tid < off) red[tid] += red[tid + off];
                __syncthreads();
            }
            if (tid == 0) g_stop = (red[0] * (1.0f / 16.0f) < 0.1f) ? 1 : 0;
        }
        grid_sync(++bar);
        if (*((volatile int*)&g_stop)) break;
    }

    // ---- final: cost = -eps/16 * sum_r a_r * sum_j (K ln K) b_j ----
    for (int idx = tid; idx < (nslot << 10); idx += SKT)
        sb_b[idx] = __ldcg(&g_b[(b0 << 10) + idx]);
    __syncthreads();
    for (int lr = warp; lr < nrows; lr += 16) {
        int r = rs + lr;
        const float* bs = sb_b + (((r >> 10) - b0) << 10);
        const uint4* Kr = (const uint4*)(g_Kh + ((size_t)r << 10));
        float acc = 0.f;
        #pragma unroll
        for (int k = 0; k < 4; k++) {
            int u = lane + (k << 5);
            uint4 v = Kr[u];
            const float4* bp = (const float4*)(bs + (u << 3));
            float4 q0 = bp[0], q1 = bp[1];
            float2 f0 = __half22float2(*(__half2*)&v.x);
            float2 f1 = __half22float2(*(__half2*)&v.y);
            float2 f2 = __half22float2(*(__half2*)&v.z);
            float2 f3 = __half22float2(*(__half2*)&v.w);
            float t0 = (f0.x > 0.f) ? f0.x * __logf(f0.x) : 0.f;
            float t1 = (f0.y > 0.f) ? f0.y * __logf(f0.y) : 0.f;
            float t2 = (f1.x > 0.f) ? f1.x * __logf(f1.x) : 0.f;
            float t3 = (f1.y > 0.f) ? f1.y * __logf(f1.y) : 0.f;
            float t4 = (f2.x > 0.f) ? f2.x * __logf(f2.x) : 0.f;
            float t5 = (f2.y > 0.f) ? f2.y * __logf(f2.y) : 0.f;
            float t6 = (f3.x > 0.f) ? f3.x * __logf(f3.x) : 0.f;
            float t7 = (f3.y > 0.f) ? f3.y * __logf(f3.y) : 0.f;
            acc = fmaf(t0, q0.x, fmaf(t1, q0.y, fmaf(t2, q0.z, fmaf(t3, q0.w, acc))));
            acc = fmaf(t4, q1.x, fmaf(t5, q1.y, fmaf(t6, q1.z, fmaf(t7, q1.w, acc))));
        }
        #pragma unroll
        for (int o = 16; o; o >>= 1) acc += __shfl_xor_sync(0xffffffffu, acc, o);
        if (lane == 0)
            __stcg(&g_du[r], a_loc[lr] * acc);
    }
    grid_sync(++bar);
    if (blk == 0) {
        float s = 0.f;
        #pragma unroll
        for (int k = 0; k < 32; k++) s += __ldcg(&g_du[tid + (k << 9)]);
        red[tid] = s;
        __syncthreads();
        for (int off = 256; off; off >>= 1) {
            if (tid < off) red[tid] += red[tid + off];
            __syncthreads();
        }
        if (tid == 0) out[0] = red[0] * (-EPS_ / 16.0f);
    }
}

// ---------------- launch ----------------
extern "C" void kernel_launch(void* const* d_in, const int* in_sizes, int n_in,
                              void* d_out, int out_size) {
    const float* x = (const float*)d_in[0];
    const float* y = (const float*)d_in[1];
    (void)in_sizes; (void)n_in; (void)out_size;

    cudaFuncSetAttribute(sinkhorn_kernel,
                         cudaFuncAttributeMaxDynamicSharedMemorySize, SK_SMEM_BYTES);

    softmax_kernel<<<1024, 256>>>(x, y);
    dim3 gc(16, 8, 16);   // (j-tiles of 64, i-tiles of 128, batch)
    cost_kernel<<<gc, 256>>>();
    sinkhorn_kernel<<<NBLK, SKT, SK_SMEM_BYTES>>>((float*)d_out);
}

// round 11
// speedup vs baseline: 1.3058x; 1.0004x over previous
#include <cuda_runtime.h>
#include <cuda_fp16.h>
#include <math.h>
#include <stdint.h>

// ---------------- problem constants ----------------
#define B_  16
#define N_  1024
#define D_  64
#define EPS_ 0.1f
#define TOTAL_ROWS (B_*N_)        // 16384
#define NBLK 148
#define SKT 512                   // sinkhorn threads (16 warps)
#define CHUNK 111                 // ceil(16384/148)
#define BAR_STRIDE 32             // 128B between barrier flags
// dyn smem: sb_b 2048f + wp 16*1024f + red 512f
#define SK_SMEM_FLOATS (2048 + 16*1024 + 512)
#define SK_SMEM_BYTES  (SK_SMEM_FLOATS * 4)

// ---------------- device scratch (static, no allocs) ----------------
__device__ __half g_sxh[TOTAL_ROWS*D_];            // softmax(x) fp16  2MB
__device__ __half g_syh[TOTAL_ROWS*D_];            // softmax(y) fp16  2MB
__device__ float  g_x2[TOTAL_ROWS];
__device__ float  g_y2[TOTAL_ROWS];
__device__ __half g_Kh[(size_t)B_*N_*N_];          // K = exp(-10C) fp16, 32MB
__device__ float  g_b[TOTAL_ROWS];
__device__ float  g_du[TOTAL_ROWS];
__device__ float  g_tp[NBLK*2048];                 // per-block col partials (2 slots)
__device__ unsigned g_flags[NBLK*BAR_STRIDE];      // barrier flags (monotonic)
__device__ unsigned g_gen2;                        // barrier generation
__device__ int g_stop;

// ---------------- helpers ----------------
__device__ __forceinline__ uint32_t smem_u32(const void* p) {
    uint32_t a;
    asm("{ .reg .u64 t; cvta.to.shared.u64 t, %1; cvt.u32.u64 %0, t; }" : "=r"(a) : "l"(p));
    return a;
}
__device__ __forceinline__ void ldsm_x4(uint32_t& r0, uint32_t& r1, uint32_t& r2, uint32_t& r3,
                                        uint32_t addr) {
    asm volatile("ldmatrix.sync.aligned.m8n8.x4.shared.b16 {%0,%1,%2,%3}, [%4];"
                 : "=r"(r0), "=r"(r1), "=r"(r2), "=r"(r3) : "r"(addr));
}
__device__ __forceinline__ void mma16816(float* c, const uint32_t* a, const uint32_t* b) {
    asm volatile(
        "mma.sync.aligned.m16n8k16.row.col.f32.f16.f16.f32 "
        "{%0,%1,%2,%3}, {%4,%5,%6,%7}, {%8,%9}, {%0,%1,%2,%3};"
        : "+f"(c[0]), "+f"(c[1]), "+f"(c[2]), "+f"(c[3])
        : "r"(a[0]), "r"(a[1]), "r"(a[2]), "r"(a[3]), "r"(b[0]), "r"(b[1]));
}

// ---------------- softmax: 4 rows/warp, no-max-sub (R9) -------------------
__global__ __launch_bounds__(256) void softmax_kernel(const float* __restrict__ x,
                                                      const float* __restrict__ y) {
    int w    = (blockIdx.x * blockDim.x + threadIdx.x) >> 5;
    int lane = threadIdx.x & 31;
    const float* src; __half* dst; float* nrm; int r0;
    if (w < 4096) { src = x; dst = g_sxh; nrm = g_x2; r0 = w << 2; }
    else          { src = y; dst = g_syh; nrm = g_y2; r0 = (w - 4096) << 2; }
    float2 v[4];
    #pragma unroll
    for (int q = 0; q < 4; q++)
        v[q] = ((const float2*)(src + (size_t)(r0 + q) * D_))[lane];
    float e0[4], e1[4], s[4], n[4];
    #pragma unroll
    for (int q = 0; q < 4; q++) {
        e0[q] = __expf(v[q].x);
        e1[q] = __expf(v[q].y);
        s[q] = e0[q] + e1[q];
        n[q] = fmaf(e0[q], e0[q], e1[q] * e1[q]);
    }
    #pragma unroll
    for (int o = 16; o; o >>= 1)
        #pragma unroll
        for (int q = 0; q < 4; q++) {
            s[q] += __shfl_xor_sync(0xffffffffu, s[q], o);
            n[q] += __shfl_xor_sync(0xffffffffu, n[q], o);
        }
    #pragma unroll
    for (int q = 0; q < 4; q++) {
        float inv = 1.0f / s[q];
        ((__half2*)dst)[(size_t)(r0 + q) * 32 + lane] =
            __floats2half2_rn(e0[q] * inv, e1[q] * inv);
    }
    if (lane == 0)
        #pragma unroll
        for (int q = 0; q < 4; q++) nrm[r0 + q] = n[q] / (s[q] * s[q]);
}

// ---------------- cost kernel: HMMA + fused exp -> fp16 K (R4) ------------
__global__ __launch_bounds__(256) void cost_kernel() {
    __shared__ __half As[128][72];
    __shared__ __half Bs[64][72];
    __shared__ float  ys2[64];
    const int tid = threadIdx.x, warp = tid >> 5, lane = tid & 31;
    const int jt = blockIdx.x, it = blockIdx.y, b = blockIdx.z;
    const int i_base = (b << 10) + (it << 7);
    const int j_base = (b << 10) + (jt << 6);

    #pragma unroll
    for (int q = 0; q < 4; q++) {
        int idx = tid + (q << 8);
        int r = idx >> 3, ch = idx & 7;
        *(uint4*)&As[r][ch << 3] = ((const uint4*)(g_sxh + (size_t)(i_base + r) * D_))[ch];
    }
    #pragma unroll
    for (int q = 0; q < 2; q++) {
        int idx = tid + (q << 8);
        int r = idx >> 3, ch = idx & 7;
        *(uint4*)&Bs[r][ch << 3] = ((const uint4*)(g_syh + (size_t)(j_base + r) * D_))[ch];
    }
    if (tid < 64) ys2[tid] = g_y2[j_base + tid];
    __syncthreads();

    const int wr = warp & 3, wc = warp >> 2;
    const int m0 = wr << 5, n0 = wc << 5;

    float acc[2][4][4];
    #pragma unroll
    for (int mt = 0; mt < 2; mt++)
        #pragma unroll
        for (int nt = 0; nt < 4; nt++)
            #pragma unroll
            for (int e = 0; e < 4; e++) acc[mt][nt][e] = 0.f;

    #pragma unroll
    for (int ks = 0; ks < 4; ks++) {
        const int k0 = ks << 4;
        uint32_t af[2][4], bf[4][2];
        #pragma unroll
        for (int mt = 0; mt < 2; mt++) {
            uint32_t addr = smem_u32(&As[m0 + (mt << 4) + (lane & 15)][k0 + ((lane >> 4) << 3)]);
            ldsm_x4(af[mt][0], af[mt][1], af[mt][2], af[mt][3], addr);
        }
        #pragma unroll
        for (int np = 0; np < 2; np++) {
            int mat = lane >> 3, rin = lane & 7;
            int row = n0 + (np << 4) + ((mat >> 1) << 3) + rin;
            int col = k0 + ((mat & 1) << 3);
            uint32_t addr = smem_u32(&Bs[row][col]);
            uint32_t r0, r1, r2, r3;
            ldsm_x4(r0, r1, r2, r3, addr);
            bf[np * 2][0] = r0; bf[np * 2][1] = r1;
            bf[np * 2 + 1][0] = r2; bf[np * 2 + 1][1] = r3;
        }
        #pragma unroll
        for (int mt = 0; mt < 2; mt++)
            #pragma unroll
            for (int nt = 0; nt < 4; nt++)
                mma16816(acc[mt][nt], af[mt], bf[nt]);
    }

    const int g = lane >> 2, tq = lane & 3;
    #pragma unroll
    for (int mt = 0; mt < 2; mt++) {
        int gi0 = i_base + m0 + (mt << 4) + g;
        int gi1 = gi0 + 8;
        float xi0 = g_x2[gi0], xi1 = g_x2[gi1];
        __half* d0 = g_Kh + ((size_t)gi0 << 10) + (jt << 6);
        __half* d1 = g_Kh + ((size_t)gi1 << 10) + (jt << 6);
        #pragma unroll
        for (int nt = 0; nt < 4; nt++) {
            int jl = n0 + (nt << 3) + (tq << 1);
            float yj0 = ys2[jl], yj1 = ys2[jl + 1];
            float c00 = xi0 + yj0 - 2.0f * acc[mt][nt][0];
            float c01 = xi0 + yj1 - 2.0f * acc[mt][nt][1];
            float c10 = xi1 + yj0 - 2.0f * acc[mt][nt][2];
            float c11 = xi1 + yj1 - 2.0f * acc[mt][nt][3];
            *(__half2*)(d0 + jl) = __floats2half2_rn(__expf(-10.0f * c00), __expf(-10.0f * c01));
            *(__half2*)(d1 + jl) = __floats2half2_rn(__expf(-10.0f * c10), __expf(-10.0f * c11));
        }
    }
}

// ---------------- flag-array grid barrier ----------------
__device__ __forceinline__ void grid_sync(unsigned tgt) {
    __syncthreads();
    if (blockIdx.x == 0) {
        if (threadIdx.x > 0 && threadIdx.x < NBLK) {
            while (((volatile unsigned*)g_flags)[threadIdx.x * BAR_STRIDE] < tgt) { }
        }
        __threadfence();
        __syncthreads();
        if (threadIdx.x == 0) *(volatile unsigned*)&g_gen2 = tgt;
        __syncthreads();
    } else {
        if (threadIdx.x == 0) {
            __threadfence();
            ((volatile unsigned*)g_flags)[blockIdx.x * BAR_STRIDE] = tgt;
            while (*(volatile unsigned*)&g_gen2 < tgt) { }
            __threadfence();
        }
        __syncthreads();
    }
}

// ---------------- fused persistent Sinkhorn: ONE K sweep per iteration ----
// 512 thr (16 warps). Each warp: row pair -> dot with b (s_i), a-update,
// then immediate col accumulation a_new*K into 32 per-lane fp32 regs.
__global__ __launch_bounds__(SKT, 1) void sinkhorn_kernel(float* __restrict__ out) {
    extern __shared__ float sm[];
    float* sb_b = sm;                 // 2048
    float* wp   = sm + 2048;          // 16*1024 per-warp col partials
    float* red  = sm + 2048 + 16384;  // 512
    __shared__ float a_loc[128];
    const int tid = threadIdx.x, blk = blockIdx.x;
    const int lane = tid & 31, warp = tid >> 5;
    const float mu = 1.0f / 1024.0f + 1e-8f;
    const float log_mu = logf(mu);

    unsigned bar = *(volatile unsigned*)&g_gen2;

    const int rs = blk * CHUNK;
    const int re = min(rs + CHUNK, TOTAL_ROWS);
    const int nrows = re - rs;
    const int b0 = rs >> 10;
    const int nslot = ((re - 1) >> 10) - b0 + 1;   // 1 or 2

    if (tid < 128) a_loc[tid] = 1.0f;
    if (blk < 16)
        for (int j = tid; j < 1024; j += SKT) g_b[(blk << 10) + j] = 1.0f;
    if (blk == 0 && tid == 0) g_stop = 0;
    grid_sync(++bar);

    for (int it = 0; it < 100; ++it) {
        // stage b for this block's batch slots
        for (int idx = tid; idx < (nslot << 10); idx += SKT)
            sb_b[idx] = __ldcg(&g_b[(b0 << 10) + idx]);
        __syncthreads();

        for (int slot = 0; slot < nslot; ++slot) {
            const int seg_s = max(0, ((b0 + slot) << 10) - rs);
            const int seg_e = min(nrows, ((b0 + slot + 1) << 10) - rs);
            const float* bs = sb_b + (slot << 10);
            // hoist this lane's b values (32 floats, fixed cols across rows)
            float4 bq[8];
            #pragma unroll
            for (int k = 0; k < 4; k++) {
                const float* bp = bs + ((lane + (k << 5)) << 3);
                bq[k * 2]     = *(const float4*)bp;
                bq[k * 2 + 1] = *(const float4*)(bp + 4);
            }
            float ca[32];
            #pragma unroll
            for (int e = 0; e < 32; e++) ca[e] = 0.f;

            for (int lr = seg_s + warp; lr < seg_e; lr += 32) {
                const int lrB = lr + 16;
                const bool hasB = (lrB < seg_e);
                uint4 va[4], vb[4];
                const uint4* KA = (const uint4*)(g_Kh + ((size_t)(rs + lr) << 10));
                #pragma unroll
                for (int k = 0; k < 4; k++) va[k] = KA[lane + (k << 5)];
                if (hasB) {
                    const uint4* KB = (const uint4*)(g_Kh + ((size_t)(rs + lrB) << 10));
                    #pragma unroll
                    for (int k = 0; k < 4; k++) vb[k] = KB[lane + (k << 5)];
                }
                // ---- dot A (R4-identical chain order) ----
                float accA = 0.f;
                #pragma unroll
                for (int k = 0; k < 4; k++) {
                    float2 f0 = __half22float2(*(__half2*)&va[k].x);
                    float2 f1 = __half22float2(*(__half2*)&va[k].y);
                    float2 f2 = __half22float2(*(__half2*)&va[k].z);
                    float2 f3 = __half22float2(*(__half2*)&va[k].w);
                    float4 q0 = bq[k * 2], q1 = bq[k * 2 + 1];
                    accA = fmaf(f0.x, q0.x, fmaf(f0.y, q0.y, fmaf(f1.x, q0.z, fmaf(f1.y, q0.w, accA))));
                    accA = fmaf(f2.x, q1.x, fmaf(f2.y, q1.y, fmaf(f3.x, q1.z, fmaf(f3.y, q1.w, accA))));
                }
                float accB = 0.f;
                if (hasB) {
                    #pragma unroll
                    for (int k = 0; k < 4; k++) {
                        float2 f0 = __half22float2(*(__half2*)&vb[k].x);
                        float2 f1 = __half22float2(*(__half2*)&vb[k].y);
                        float2 f2 = __half22float2(*(__half2*)&vb[k].z);
                        float2 f3 = __half22float2(*(__half2*)&vb[k].w);
                        float4 q0 = bq[k * 2], q1 = bq[k * 2 + 1];
                        accB = fmaf(f0.x, q0.x, fmaf(f0.y, q0.y, fmaf(f1.x, q0.z, fmaf(f1.y, q0.w, accB))));
                        accB = fmaf(f2.x, q1.x, fmaf(f2.y, q1.y, fmaf(f3.x, q1.z, fmaf(f3.y, q1.w, accB))));
                    }
                }
                #pragma unroll
                for (int o = 16; o; o >>= 1) {
                    accA += __shfl_xor_sync(0xffffffffu, accA, o);
                    accB += __shfl_xor_sync(0xffffffffu, accB, o);
                }
                float aA = 0.f, aB = 0.f;
                if (lane == 0) {
                    float aold = a_loc[lr];
                    float as = fmaf(aold, accA, 1e-6f);
                    __stcg(&g_du[rs + lr], fabsf(EPS_ * (log_mu - __logf(as))));
                    aA = mu * aold / as;
                    a_loc[lr] = aA;
                    if (hasB) {
                        float bold = a_loc[lrB];
                        float bsv = fmaf(bold, accB, 1e-6f);
                        __stcg(&g_du[rs + lrB], fabsf(EPS_ * (log_mu - __logf(bsv))));
                        aB = mu * bold / bsv;
                        a_loc[lrB] = aB;
                    }
                }
                aA = __shfl_sync(0xffffffffu, aA, 0);
                aB = __shfl_sync(0xffffffffu, aB, 0);
                // ---- col accumulation from register-held K ----
                #pragma unroll
                for (int k = 0; k < 4; k++) {
                    float2 f0 = __half22float2(*(__half2*)&va[k].x);
                    float2 f1 = __half22float2(*(__half2*)&va[k].y);
                    float2 f2 = __half22float2(*(__half2*)&va[k].z);
                    float2 f3 = __half22float2(*(__half2*)&va[k].w);
                    ca[k*8+0] = fmaf(f0.x, aA, ca[k*8+0]); ca[k*8+1] = fmaf(f0.y, aA, ca[k*8+1]);
                    ca[k*8+2] = fmaf(f1.x, aA, ca[k*8+2]); ca[k*8+3] = fmaf(f1.y, aA, ca[k*8+3]);
                    ca[k*8+4] = fmaf(f2.x, aA, ca[k*8+4]); ca[k*8+5] = fmaf(f2.y, aA, ca[k*8+5]);
                    ca[k*8+6] = fmaf(f3.x, aA, ca[k*8+6]); ca[k*8+7] = fmaf(f3.y, aA, ca[k*8+7]);
                }
                if (hasB) {
                    #pragma unroll
                    for (int k = 0; k < 4; k++) {
                        float2 f0 = __half22float2(*(__half2*)&vb[k].x);
                        float2 f1 = __half22float2(*(__half2*)&vb[k].y);
                        float2 f2 = __half22float2(*(__half2*)&vb[k].z);
                        float2 f3 = __half22float2(*(__half2*)&vb[k].w);
                        ca[k*8+0] = fmaf(f0.x, aB, ca[k*8+0]); ca[k*8+1] = fmaf(f0.y, aB, ca[k*8+1]);
                        ca[k*8+2] = fmaf(f1.x, aB, ca[k*8+2]); ca[k*8+3] = fmaf(f1.y, aB, ca[k*8+3]);
                        ca[k*8+4] = fmaf(f2.x, aB, ca[k*8+4]); ca[k*8+5] = fmaf(f2.y, aB, ca[k*8+5]);
                        ca[k*8+6] = fmaf(f3.x, aB, ca[k*8+6]); ca[k*8+7] = fmaf(f3.y, aB, ca[k*8+7]);
                    }
                }
            }
            // ---- flush warp partials, reduce 16 warps -> g_tp[blk][slot] ----
            #pragma unroll
            for (int k = 0; k < 4; k++) {
                int cb = (lane + (k << 5)) << 3;
                *(float4*)&wp[(warp << 10) + cb]     = make_float4(ca[k*8+0], ca[k*8+1], ca[k*8+2], ca[k*8+3]);
                *(float4*)&wp[(warp << 10) + cb + 4] = make_float4(ca[k*8+4], ca[k*8+5], ca[k*8+6], ca[k*8+7]);
            }
            __syncthreads();
            for (int j = tid; j < 1024; j += SKT) {
                float t = 0.f;
                #pragma unroll
                for (int w = 0; w < 16; w++) t += wp[(w << 10) + j];
                __stcg(&g_tp[blk * 2048 + (slot << 10) + j], t);
            }
            __syncthreads();
        }
        grid_sync(++bar);

        // ---- b update (blocks 0..15, one batch each) ; err on block 16 ----
        if (blk < 16) {
            const int jf = (blk << 10) / CHUNK;
            const int jl = min(((blk << 10) + 1023) / CHUNK, NBLK - 1);
            for (int j = tid; j < 1024; j += SKT) {
                float t = 0.f;
                for (int q = jf; q <= jl; q++) {
                    int slot = blk - ((q * CHUNK) >> 10);
                    t += __ldcg(&g_tp[q * 2048 + (slot << 10) + j]);
                }
                int gj = (blk << 10) + j;
                float bold = __ldcg(&g_b[gj]);
                float bt = fmaf(bold, t, 1e-6f);
                __stcg(&g_b[gj], mu * bold / bt);
            }
        } else if (blk == 16) {
            float s = 0.f;
            #pragma unroll
            for (int k = 0; k < 32; k++) s += __ldcg(&g_du[tid + (k << 9)]);
            red[tid] = s;
            __syncthreads();
            for (int off = 256; off; off >>= 1) {
                if (tid < off) red[tid] += red[tid + off];
                __syncthreads();
            }
            if (tid == 0) g_stop = (red[0] * (1.0f / 16.0f) < 0.1f) ? 1 : 0;
        }
        grid_sync(++bar);
        if (*((volatile int*)&g_stop)) break;
    }

    // ---- final: cost = -eps/16 * sum_r a_r * sum_j (K ln K) b_j ----
    for (int idx = tid; idx < (nslot << 10); idx += SKT)
        sb_b[idx] = __ldcg(&g_b[(b0 << 10) + idx]);
    __syncthreads();
    for (int lr = warp; lr < nrows; lr += 16) {
        int r = rs + lr;
        const float* bs = sb_b + (((r >> 10) - b0) << 10);
        const uint4* Kr = (const uint4*)(g_Kh + ((size_t)r << 10));
        float acc = 0.f;
        #pragma unroll
        for (int k = 0; k < 4; k++) {
            int u = lane + (k << 5);
            uint4 v = Kr[u];
            const float4* bp = (const float4*)(bs + (u << 3));
            float4 q0 = bp[0], q1 = bp[1];
            float2 f0 = __half22float2(*(__half2*)&v.x);
            float2 f1 = __half22float2(*(__half2*)&v.y);
            float2 f2 = __half22float2(*(__half2*)&v.z);
            float2 f3 = __half22float2(*(__half2*)&v.w);
            float t0 = (f0.x > 0.f) ? f0.x * __logf(f0.x) : 0.f;
            float t1 = (f0.y > 0.f) ? f0.y * __logf(f0.y) : 0.f;
            float t2 = (f1.x > 0.f) ? f1.x * __logf(f1.x) : 0.f;
            float t3 = (f1.y > 0.f) ? f1.y * __logf(f1.y) : 0.f;
            float t4 = (f2.x > 0.f) ? f2.x * __logf(f2.x) : 0.f;
            float t5 = (f2.y > 0.f) ? f2.y * __logf(f2.y) : 0.f;
            float t6 = (f3.x > 0.f) ? f3.x * __logf(f3.x) : 0.f;
            float t7 = (f3.y > 0.f) ? f3.y * __logf(f3.y) : 0.f;
            acc = fmaf(t0, q0.x, fmaf(t1, q0.y, fmaf(t2, q0.z, fmaf(t3, q0.w, acc))));
            acc = fmaf(t4, q1.x, fmaf(t5, q1.y, fmaf(t6, q1.z, fmaf(t7, q1.w, acc))));
        }
        #pragma unroll
        for (int o = 16; o; o >>= 1) acc += __shfl_xor_sync(0xffffffffu, acc, o);
        if (lane == 0)
            __stcg(&g_du[r], a_loc[lr] * acc);
    }
    grid_sync(++bar);
    if (blk == 0) {
        float s = 0.f;
        #pragma unroll
        for (int k = 0; k < 32; k++) s += __ldcg(&g_du[tid + (k << 9)]);
        red[tid] = s;
        __syncthreads();
        for (int off = 256; off; off >>= 1) {
            if (tid < off) red[tid] += red[tid + off];
            __syncthreads();
        }
        if (tid == 0) out[0] = red[0] * (-EPS_ / 16.0f);
    }
}

// ---------------- launch ----------------
extern "C" void kernel_launch(void* const* d_in, const int* in_sizes, int n_in,
                              void* d_out, int out_size) {
    const float* x = (const float*)d_in[0];
    const float* y = (const float*)d_in[1];
    (void)in_sizes; (void)n_in; (void)out_size;

    cudaFuncSetAttribute(sinkhorn_kernel,
                         cudaFuncAttributeMaxDynamicSharedMemorySize, SK_SMEM_BYTES);

    softmax_kernel<<<1024, 256>>>(x, y);
    dim3 gc(16, 8, 16);   // (j-tiles of 64, i-tiles of 128, batch)
    cost_kernel<<<gc, 256>>>();
    sinkhorn_kernel<<<NBLK, SKT, SK_SMEM_BYTES>>>((float*)d_out);
}

// round 12
// speedup vs baseline: 1.3063x; 1.0004x over previous
#include <cuda_runtime.h>
#include <cuda_fp16.h>
#include <math.h>
#include <stdint.h>

// ---------------- problem constants ----------------
#define B_  16
#define N_  1024
#define D_  64
#define EPS_ 0.1f
#define TOTAL_ROWS (B_*N_)        // 16384
#define NBLK 148
#define SKT 512                   // sinkhorn threads (16 warps)
#define CHUNK 111                 // ceil(16384/148)
#define BAR_STRIDE 32             // 128B between barrier flags
// dyn smem: sb_b 2048f + wp 16*1024f + red 512f
#define SK_SMEM_FLOATS (2048 + 16*1024 + 512)
#define SK_SMEM_BYTES  (SK_SMEM_FLOATS * 4)

// ---------------- device scratch (static, no allocs) ----------------
__device__ __half g_sxh[TOTAL_ROWS*D_];            // softmax(x) fp16  2MB
__device__ __half g_syh[TOTAL_ROWS*D_];            // softmax(y) fp16  2MB
__device__ float  g_x2[TOTAL_ROWS];
__device__ float  g_y2[TOTAL_ROWS];
__device__ __half g_Kh[(size_t)B_*N_*N_];          // K = exp(-10C) fp16, 32MB
__device__ float  g_b[TOTAL_ROWS];
__device__ float  g_du[TOTAL_ROWS];
__device__ float  g_tp[NBLK*2048];                 // per-block col partials (2 slots)
__device__ unsigned g_flags[NBLK*BAR_STRIDE];      // barrier flags (monotonic)
__device__ unsigned g_gen2;                        // barrier generation
__device__ int g_stop;

// ---------------- helpers ----------------
__device__ __forceinline__ uint32_t smem_u32(const void* p) {
    uint32_t a;
    asm("{ .reg .u64 t; cvta.to.shared.u64 t, %1; cvt.u32.u64 %0, t; }" : "=r"(a) : "l"(p));
    return a;
}
__device__ __forceinline__ void ldsm_x4(uint32_t& r0, uint32_t& r1, uint32_t& r2, uint32_t& r3,
                                        uint32_t addr) {
    asm volatile("ldmatrix.sync.aligned.m8n8.x4.shared.b16 {%0,%1,%2,%3}, [%4];"
                 : "=r"(r0), "=r"(r1), "=r"(r2), "=r"(r3) : "r"(addr));
}
__device__ __forceinline__ void mma16816(float* c, const uint32_t* a, const uint32_t* b) {
    asm volatile(
        "mma.sync.aligned.m16n8k16.row.col.f32.f16.f16.f32 "
        "{%0,%1,%2,%3}, {%4,%5,%6,%7}, {%8,%9}, {%0,%1,%2,%3};"
        : "+f"(c[0]), "+f"(c[1]), "+f"(c[2]), "+f"(c[3])
        : "r"(a[0]), "r"(a[1]), "r"(a[2]), "r"(a[3]), "r"(b[0]), "r"(b[1]));
}

// ---------------- softmax: 4 rows/warp, no-max-sub (R9) -------------------
__global__ __launch_bounds__(256) void softmax_kernel(const float* __restrict__ x,
                                                      const float* __restrict__ y) {
    int w    = (blockIdx.x * blockDim.x + threadIdx.x) >> 5;
    int lane = threadIdx.x & 31;
    const float* src; __half* dst; float* nrm; int r0;
    if (w < 4096) { src = x; dst = g_sxh; nrm = g_x2; r0 = w << 2; }
    else          { src = y; dst = g_syh; nrm = g_y2; r0 = (w - 4096) << 2; }
    float2 v[4];
    #pragma unroll
    for (int q = 0; q < 4; q++)
        v[q] = ((const float2*)(src + (size_t)(r0 + q) * D_))[lane];
    float e0[4], e1[4], s[4], n[4];
    #pragma unroll
    for (int q = 0; q < 4; q++) {
        e0[q] = __expf(v[q].x);
        e1[q] = __expf(v[q].y);
        s[q] = e0[q] + e1[q];
        n[q] = fmaf(e0[q], e0[q], e1[q] * e1[q]);
    }
    #pragma unroll
    for (int o = 16; o; o >>= 1)
        #pragma unroll
        for (int q = 0; q < 4; q++) {
            s[q] += __shfl_xor_sync(0xffffffffu, s[q], o);
            n[q] += __shfl_xor_sync(0xffffffffu, n[q], o);
        }
    #pragma unroll
    for (int q = 0; q < 4; q++) {
        float inv = 1.0f / s[q];
        ((__half2*)dst)[(size_t)(r0 + q) * 32 + lane] =
            __floats2half2_rn(e0[q] * inv, e1[q] * inv);
    }
    if (lane == 0)
        #pragma unroll
        for (int q = 0; q < 4; q++) nrm[r0 + q] = n[q] / (s[q] * s[q]);
}

// ---------------- cost kernel: HMMA + fused exp -> fp16 K (R4) ------------
__global__ __launch_bounds__(256) void cost_kernel() {
    __shared__ __half As[128][72];
    __shared__ __half Bs[64][72];
    __shared__ float  ys2[64];
    const int tid = threadIdx.x, warp = tid >> 5, lane = tid & 31;
    const int jt = blockIdx.x, it = blockIdx.y, b = blockIdx.z;
    const int i_base = (b << 10) + (it << 7);
    const int j_base = (b << 10) + (jt << 6);

    #pragma unroll
    for (int q = 0; q < 4; q++) {
        int idx = tid + (q << 8);
        int r = idx >> 3, ch = idx & 7;
        *(uint4*)&As[r][ch << 3] = ((const uint4*)(g_sxh + (size_t)(i_base + r) * D_))[ch];
    }
    #pragma unroll
    for (int q = 0; q < 2; q++) {
        int idx = tid + (q << 8);
        int r = idx >> 3, ch = idx & 7;
        *(uint4*)&Bs[r][ch << 3] = ((const uint4*)(g_syh + (size_t)(j_base + r) * D_))[ch];
    }
    if (tid < 64) ys2[tid] = g_y2[j_base + tid];
    __syncthreads();

    const int wr = warp & 3, wc = warp >> 2;
    const int m0 = wr << 5, n0 = wc << 5;

    float acc[2][4][4];
    #pragma unroll
    for (int mt = 0; mt < 2; mt++)
        #pragma unroll
        for (int nt = 0; nt < 4; nt++)
            #pragma unroll
            for (int e = 0; e < 4; e++) acc[mt][nt][e] = 0.f;

    #pragma unroll
    for (int ks = 0; ks < 4; ks++) {
        const int k0 = ks << 4;
        uint32_t af[2][4], bf[4][2];
        #pragma unroll
        for (int mt = 0; mt < 2; mt++) {
            uint32_t addr = smem_u32(&As[m0 + (mt << 4) + (lane & 15)][k0 + ((lane >> 4) << 3)]);
            ldsm_x4(af[mt][0], af[mt][1], af[mt][2], af[mt][3], addr);
        }
        #pragma unroll
        for (int np = 0; np < 2; np++) {
            int mat = lane >> 3, rin = lane & 7;
            int row = n0 + (np << 4) + ((mat >> 1) << 3) + rin;
            int col = k0 + ((mat & 1) << 3);
            uint32_t addr = smem_u32(&Bs[row][col]);
            uint32_t r0, r1, r2, r3;
            ldsm_x4(r0, r1, r2, r3, addr);
            bf[np * 2][0] = r0; bf[np * 2][1] = r1;
            bf[np * 2 + 1][0] = r2; bf[np * 2 + 1][1] = r3;
        }
        #pragma unroll
        for (int mt = 0; mt < 2; mt++)
            #pragma unroll
            for (int nt = 0; nt < 4; nt++)
                mma16816(acc[mt][nt], af[mt], bf[nt]);
    }

    const int g = lane >> 2, tq = lane & 3;
    #pragma unroll
    for (int mt = 0; mt < 2; mt++) {
        int gi0 = i_base + m0 + (mt << 4) + g;
        int gi1 = gi0 + 8;
        float xi0 = g_x2[gi0], xi1 = g_x2[gi1];
        __half* d0 = g_Kh + ((size_t)gi0 << 10) + (jt << 6);
        __half* d1 = g_Kh + ((size_t)gi1 << 10) + (jt << 6);
        #pragma unroll
        for (int nt = 0; nt < 4; nt++) {
            int jl = n0 + (nt << 3) + (tq << 1);
            float yj0 = ys2[jl], yj1 = ys2[jl + 1];
            float c00 = xi0 + yj0 - 2.0f * acc[mt][nt][0];
            float c01 = xi0 + yj1 - 2.0f * acc[mt][nt][1];
            float c10 = xi1 + yj0 - 2.0f * acc[mt][nt][2];
            float c11 = xi1 + yj1 - 2.0f * acc[mt][nt][3];
            *(__half2*)(d0 + jl) = __floats2half2_rn(__expf(-10.0f * c00), __expf(-10.0f * c01));
            *(__half2*)(d1 + jl) = __floats2half2_rn(__expf(-10.0f * c10), __expf(-10.0f * c11));
        }
    }
}

// ---------------- flag-array grid barrier ----------------
__device__ __forceinline__ void grid_sync(unsigned tgt) {
    __syncthreads();
    if (blockIdx.x == 0) {
        if (threadIdx.x > 0 && threadIdx.x < NBLK) {
            while (((volatile unsigned*)g_flags)[threadIdx.x * BAR_STRIDE] < tgt) { }
        }
        __threadfence();
        __syncthreads();
        if (threadIdx.x == 0) *(volatile unsigned*)&g_gen2 = tgt;
        __syncthreads();
    } else {
        if (threadIdx.x == 0) {
            __threadfence();
            ((volatile unsigned*)g_flags)[blockIdx.x * BAR_STRIDE] = tgt;
            while (*(volatile unsigned*)&g_gen2 < tgt) { }
            __threadfence();
        }
        __syncthreads();
    }
}

// ---------------- fused persistent Sinkhorn: ONE K sweep per iteration ----
// 512 thr (16 warps). Each warp: row pair -> dot with b (s_i), a-update,
// then immediate col accumulation a_new*K into 32 per-lane fp32 regs.
__global__ __launch_bounds__(SKT, 1) void sinkhorn_kernel(float* __restrict__ out) {
    extern __shared__ float sm[];
    float* sb_b = sm;                 // 2048
    float* wp   = sm + 2048;          // 16*1024 per-warp col partials
    float* red  = sm + 2048 + 16384;  // 512
    __shared__ float a_loc[128];
    const int tid = threadIdx.x, blk = blockIdx.x;
    const int lane = tid & 31, warp = tid >> 5;
    const float mu = 1.0f / 1024.0f + 1e-8f;
    const float log_mu = logf(mu);

    unsigned bar = *(volatile unsigned*)&g_gen2;

    const int rs = blk * CHUNK;
    const int re = min(rs + CHUNK, TOTAL_ROWS);
    const int nrows = re - rs;
    const int b0 = rs >> 10;
    const int nslot = ((re - 1) >> 10) - b0 + 1;   // 1 or 2

    if (tid < 128) a_loc[tid] = 1.0f;
    if (blk < 16)
        for (int j = tid; j < 1024; j += SKT) g_b[(blk << 10) + j] = 1.0f;
    if (blk == 0 && tid == 0) g_stop = 0;
    grid_sync(++bar);

    for (int it = 0; it < 100; ++it) {
        // stage b for this block's batch slots
        for (int idx = tid; idx < (nslot << 10); idx += SKT)
            sb_b[idx] = __ldcg(&g_b[(b0 << 10) + idx]);
        __syncthreads();

        for (int slot = 0; slot < nslot; ++slot) {
            const int seg_s = max(0, ((b0 + slot) << 10) - rs);
            const int seg_e = min(nrows, ((b0 + slot + 1) << 10) - rs);
            const float* bs = sb_b + (slot << 10);
            // hoist this lane's b values (32 floats, fixed cols across rows)
            float4 bq[8];
            #pragma unroll
            for (int k = 0; k < 4; k++) {
                const float* bp = bs + ((lane + (k << 5)) << 3);
                bq[k * 2]     = *(const float4*)bp;
                bq[k * 2 + 1] = *(const float4*)(bp + 4);
            }
            float ca[32];
            #pragma unroll
            for (int e = 0; e < 32; e++) ca[e] = 0.f;

            for (int lr = seg_s + warp; lr < seg_e; lr += 32) {
                const int lrB = lr + 16;
                const bool hasB = (lrB < seg_e);
                uint4 va[4], vb[4];
                const uint4* KA = (const uint4*)(g_Kh + ((size_t)(rs + lr) << 10));
                #pragma unroll
                for (int k = 0; k < 4; k++) va[k] = KA[lane + (k << 5)];
                if (hasB) {
                    const uint4* KB = (const uint4*)(g_Kh + ((size_t)(rs + lrB) << 10));
                    #pragma unroll
                    for (int k = 0; k < 4; k++) vb[k] = KB[lane + (k << 5)];
                }
                // ---- dot A (R4-identical chain order) ----
                float accA = 0.f;
                #pragma unroll
                for (int k = 0; k < 4; k++) {
                    float2 f0 = __half22float2(*(__half2*)&va[k].x);
                    float2 f1 = __half22float2(*(__half2*)&va[k].y);
                    float2 f2 = __half22float2(*(__half2*)&va[k].z);
                    float2 f3 = __half22float2(*(__half2*)&va[k].w);
                    float4 q0 = bq[k * 2], q1 = bq[k * 2 + 1];
                    accA = fmaf(f0.x, q0.x, fmaf(f0.y, q0.y, fmaf(f1.x, q0.z, fmaf(f1.y, q0.w, accA))));
                    accA = fmaf(f2.x, q1.x, fmaf(f2.y, q1.y, fmaf(f3.x, q1.z, fmaf(f3.y, q1.w, accA))));
                }
                float accB = 0.f;
                if (hasB) {
                    #pragma unroll
                    for (int k = 0; k < 4; k++) {
                        float2 f0 = __half22float2(*(__half2*)&vb[k].x);
                        float2 f1 = __half22float2(*(__half2*)&vb[k].y);
                        float2 f2 = __half22float2(*(__half2*)&vb[k].z);
                        float2 f3 = __half22float2(*(__half2*)&vb[k].w);
                        float4 q0 = bq[k * 2], q1 = bq[k * 2 + 1];
                        accB = fmaf(f0.x, q0.x, fmaf(f0.y, q0.y, fmaf(f1.x, q0.z, fmaf(f1.y, q0.w, accB))));
                        accB = fmaf(f2.x, q1.x, fmaf(f2.y, q1.y, fmaf(f3.x, q1.z, fmaf(f3.y, q1.w, accB))));
                    }
                }
                #pragma unroll
                for (int o = 16; o; o >>= 1) {
                    accA += __shfl_xor_sync(0xffffffffu, accA, o);
                    accB += __shfl_xor_sync(0xffffffffu, accB, o);
                }
                float aA = 0.f, aB = 0.f;
                if (lane == 0) {
                    float aold = a_loc[lr];
                    float as = fmaf(aold, accA, 1e-6f);
                    __stcg(&g_du[rs + lr], fabsf(EPS_ * (log_mu - __logf(as))));
                    aA = mu * aold / as;
                    a_loc[lr] = aA;
                    if (hasB) {
                        float bold = a_loc[lrB];
                        float bsv = fmaf(bold, accB, 1e-6f);
                        __stcg(&g_du[rs + lrB], fabsf(EPS_ * (log_mu - __logf(bsv))));
                        aB = mu * bold / bsv;
                        a_loc[lrB] = aB;
                    }
                }
                aA = __shfl_sync(0xffffffffu, aA, 0);
                aB = __shfl_sync(0xffffffffu, aB, 0);
                // ---- col accumulation from register-held K ----
                #pragma unroll
                for (int k = 0; k < 4; k++) {
                    float2 f0 = __half22float2(*(__half2*)&va[k].x);
                    float2 f1 = __half22float2(*(__half2*)&va[k].y);
                    float2 f2 = __half22float2(*(__half2*)&va[k].z);
                    float2 f3 = __half22float2(*(__half2*)&va[k].w);
                    ca[k*8+0] = fmaf(f0.x, aA, ca[k*8+0]); ca[k*8+1] = fmaf(f0.y, aA, ca[k*8+1]);
                    ca[k*8+2] = fmaf(f1.x, aA, ca[k*8+2]); ca[k*8+3] = fmaf(f1.y, aA, ca[k*8+3]);
                    ca[k*8+4] = fmaf(f2.x, aA, ca[k*8+4]); ca[k*8+5] = fmaf(f2.y, aA, ca[k*8+5]);
                    ca[k*8+6] = fmaf(f3.x, aA, ca[k*8+6]); ca[k*8+7] = fmaf(f3.y, aA, ca[k*8+7]);
                }
                if (hasB) {
                    #pragma unroll
                    for (int k = 0; k < 4; k++) {
                        float2 f0 = __half22float2(*(__half2*)&vb[k].x);
                        float2 f1 = __half22float2(*(__half2*)&vb[k].y);
                        float2 f2 = __half22float2(*(__half2*)&vb[k].z);
                        float2 f3 = __half22float2(*(__half2*)&vb[k].w);
                        ca[k*8+0] = fmaf(f0.x, aB, ca[k*8+0]); ca[k*8+1] = fmaf(f0.y, aB, ca[k*8+1]);
                        ca[k*8+2] = fmaf(f1.x, aB, ca[k*8+2]); ca[k*8+3] = fmaf(f1.y, aB, ca[k*8+3]);
                        ca[k*8+4] = fmaf(f2.x, aB, ca[k*8+4]); ca[k*8+5] = fmaf(f2.y, aB, ca[k*8+5]);
                        ca[k*8+6] = fmaf(f3.x, aB, ca[k*8+6]); ca[k*8+7] = fmaf(f3.y, aB, ca[k*8+7]);
                    }
                }
            }
            // ---- flush warp partials, reduce 16 warps -> g_tp[blk][slot] ----
            #pragma unroll
            for (int k = 0; k < 4; k++) {
                int cb = (lane + (k << 5)) << 3;
                *(float4*)&wp[(warp << 10) + cb]     = make_float4(ca[k*8+0], ca[k*8+1], ca[k*8+2], ca[k*8+3]);
                *(float4*)&wp[(warp << 10) + cb + 4] = make_float4(ca[k*8+4], ca[k*8+5], ca[k*8+6], ca[k*8+7]);
            }
            __syncthreads();
            for (int j = tid; j < 1024; j += SKT) {
                float t = 0.f;
                #pragma unroll
                for (int w = 0; w < 16; w++) t += wp[(w << 10) + j];
                __stcg(&g_tp[blk * 2048 + (slot << 10) + j], t);
            }
            __syncthreads();
        }
        grid_sync(++bar);

        // ---- b update (blocks 0..15, one batch each) ; err on block 16 ----
        if (blk < 16) {
            const int jf = (blk << 10) / CHUNK;
            const int jl = min(((blk << 10) + 1023) / CHUNK, NBLK - 1);
            for (int j = tid; j < 1024; j += SKT) {
                float t = 0.f;
                for (int q = jf; q <= jl; q++) {
                    int slot = blk - ((q * CHUNK) >> 10);
                    t += __ldcg(&g_tp[q * 2048 + (slot << 10) + j]);
                }
                int gj = (blk << 10) + j;
                float bold = __ldcg(&g_b[gj]);
                float bt = fmaf(bold, t, 1e-6f);
                __stcg(&g_b[gj], mu * bold / bt);
            }
        } else if (blk == 16) {
            float s = 0.f;
            #pragma unroll
            for (int k = 0; k < 32; k++) s += __ldcg(&g_du[tid + (k << 9)]);
            red[tid] = s;
            __syncthreads();
            for (int off = 256; off; off >>= 1) {
                if (tid < off) red[tid] += red[tid + off];
                __syncthreads();
            }
            if (tid == 0) g_stop = (red[0] * (1.0f / 16.0f) < 0.1f) ? 1 : 0;
        }
        grid_sync(++bar);
        if (*((volatile int*)&g_stop)) break;
    }

    // ---- final: cost = -eps/16 * sum_r a_r * sum_j (K ln K) b_j ----
    for (int idx = tid; idx < (nslot << 10); idx += SKT)
        sb_b[idx] = __ldcg(&g_b[(b0 << 10) + idx]);
    __syncthreads();
    for (int lr = warp; lr < nrows; lr += 16) {
        int r = rs + lr;
        const float* bs = sb_b + (((r >> 10) - b0) << 10);
        const uint4* Kr = (const uint4*)(g_Kh + ((size_t)r << 10));
        float acc = 0.f;
        #pragma unroll
        for (int k = 0; k < 4; k++) {
            int u = lane + (k << 5);
            uint4 v = Kr[u];
            const float4* bp = (const float4*)(bs + (u << 3));
            float4 q0 = bp[0], q1 = bp[1];
            float2 f0 = __half22float2(*(__half2*)&v.x);
            float2 f1 = __half22float2(*(__half2*)&v.y);
            float2 f2 = __half22float2(*(__half2*)&v.z);
            float2 f3 = __half22float2(*(__half2*)&v.w);
            float t0 = (f0.x > 0.f) ? f0.x * __logf(f0.x) : 0.f;
            float t1 = (f0.y > 0.f) ? f0.y * __logf(f0.y) : 0.f;
            float t2 = (f1.x > 0.f) ? f1.x * __logf(f1.x) : 0.f;
            float t3 = (f1.y > 0.f) ? f1.y * __logf(f1.y) : 0.f;
            float t4 = (f2.x > 0.f) ? f2.x * __logf(f2.x) : 0.f;
            float t5 = (f2.y > 0.f) ? f2.y * __logf(f2.y) : 0.f;
            float t6 = (f3.x > 0.f) ? f3.x * __logf(f3.x) : 0.f;
            float t7 = (f3.y > 0.f) ? f3.y * __logf(f3.y) : 0.f;
            acc = fmaf(t0, q0.x, fmaf(t1, q0.y, fmaf(t2, q0.z, fmaf(t3, q0.w, acc))));
            acc = fmaf(t4, q1.x, fmaf(t5, q1.y, fmaf(t6, q1.z, fmaf(t7, q1.w, acc))));
        }
        #pragma unroll
        for (int o = 16; o; o >>= 1) acc += __shfl_xor_sync(0xffffffffu, acc, o);
        if (lane == 0)
            __stcg(&g_du[r], a_loc[lr] * acc);
    }
    grid_sync(++bar);
    if (blk == 0) {
        float s = 0.f;
        #pragma unroll
        for (int k = 0; k < 32; k++) s += __ldcg(&g_du[tid + (k << 9)]);
        red[tid] = s;
        __syncthreads();
        for (int off = 256; off; off >>= 1) {
            if (tid < off) red[tid] += red[tid + off];
            __syncthreads();
        }
        if (tid == 0) out[0] = red[0] * (-EPS_ / 16.0f);
    }
}

// ---------------- launch ----------------
extern "C" void kernel_launch(void* const* d_in, const int* in_sizes, int n_in,
                              void* d_out, int out_size) {
    const float* x = (const float*)d_in[0];
    const float* y = (const float*)d_in[1];
    (void)in_sizes; (void)n_in; (void)out_size;

    cudaFuncSetAttribute(sinkhorn_kernel,
                         cudaFuncAttributeMaxDynamicSharedMemorySize, SK_SMEM_BYTES);

    softmax_kernel<<<1024, 256>>>(x, y);
    dim3 gc(16, 8, 16);   // (j-tiles of 64, i-tiles of 128, batch)
    cost_kernel<<<gc, 256>>>();
    sinkhorn_kernel<<<NBLK, SKT, SK_SMEM_BYTES>>>((float*)d_out);
}